// round 1
// baseline (speedup 1.0000x reference)
#include <cuda_runtime.h>

#define NB 32768
#define ND 512
#define NSPLIT 8
#define KSPLIT (NB / NSPLIT)

// Scratch (device globals: no allocation allowed)
__device__ float g_stim_out[(size_t)NB * ND];          // 64 MB
__device__ float g_rec_out[(size_t)NB * ND];           // 64 MB
__device__ float g_gram[2][NSPLIT][ND * ND];           // 16 MB split-K partials

// ---------------------------------------------------------------------------
// packed f32x2 helpers (Blackwell sm_103a: 2x fp32 FMA per instruction)
// ---------------------------------------------------------------------------
__device__ __forceinline__ unsigned long long packdup(float x) {
    unsigned long long r;
    asm("mov.b64 %0, {%1, %1};" : "=l"(r) : "r"(__float_as_uint(x)));
    return r;
}
__device__ __forceinline__ void ffma2(unsigned long long& d,
                                      unsigned long long a,
                                      unsigned long long b) {
    asm("fma.rn.f32x2 %0, %1, %2, %0;" : "+l"(d) : "l"(a), "l"(b));
}
__device__ __forceinline__ float lo32(unsigned long long u) {
    return __uint_as_float((unsigned)u);
}
__device__ __forceinline__ float hi32(unsigned long long u) {
    return __uint_as_float((unsigned)(u >> 32));
}

// 16-deep micro-kernel: 8x8 per-thread tile, accumulators as f32x2 pairs.
template <int ASTR>
__device__ __forceinline__ void micro_tile(const float* __restrict__ As,
                                           const float* __restrict__ Bs,
                                           int tx, int ty,
                                           unsigned long long acc[8][4]) {
#pragma unroll
    for (int kk = 0; kk < 16; kk++) {
        const float* ar = As + kk * ASTR + ty * 8;
        const float* br = Bs + kk * 128 + tx * 8;
        float4 a0 = *(const float4*)ar;
        float4 a1 = *(const float4*)(ar + 4);
        ulonglong2 b0 = *(const ulonglong2*)br;
        ulonglong2 b1 = *(const ulonglong2*)(br + 4);
        unsigned long long bp0 = b0.x, bp1 = b0.y, bp2 = b1.x, bp3 = b1.y;
        float av[8] = {a0.x, a0.y, a0.z, a0.w, a1.x, a1.y, a1.z, a1.w};
#pragma unroll
        for (int m = 0; m < 8; m++) {
            unsigned long long ap = packdup(av[m]);
            ffma2(acc[m][0], ap, bp0);
            ffma2(acc[m][1], ap, bp1);
            ffma2(acc[m][2], ap, bp2);
            ffma2(acc[m][3], ap, bp3);
        }
    }
}

// ---------------------------------------------------------------------------
// K1: forward GEMMs. z=0: g_stim_out = S @ W ; z=1: g_rec_out = P @ Wr
// ---------------------------------------------------------------------------
__global__ __launch_bounds__(256) void fwd_gemm(const float* __restrict__ S,
                                                const float* __restrict__ P,
                                                const float* __restrict__ W,
                                                const float* __restrict__ Wr) {
    int mat = blockIdx.z;
    const float* A = mat ? P : S;
    const float* Bm = mat ? Wr : W;
    float* C = mat ? g_rec_out : g_stim_out;
    int n0 = blockIdx.x * 128;
    int m0 = blockIdx.y * 128;

    __shared__ __align__(16) float As[16][132];  // transposed A tile, padded
    __shared__ __align__(16) float Bs[16][128];

    int t = threadIdx.x;
    int arow = t >> 2;          // 0..63
    int acol = (t & 3) << 2;    // 0,4,8,12
    int brow = t >> 5;          // 0..7
    int bcol = (t & 31) << 2;   // 0..124
    int tx = t & 15, ty = t >> 4;

    unsigned long long acc[8][4];
#pragma unroll
    for (int i = 0; i < 8; i++)
#pragma unroll
        for (int j = 0; j < 4; j++) acc[i][j] = 0ull;

    for (int k0 = 0; k0 < ND; k0 += 16) {
#pragma unroll
        for (int r = 0; r < 2; r++) {
            int m = arow + r * 64;
            float4 v = *(const float4*)&A[(size_t)(m0 + m) * ND + k0 + acol];
            As[acol + 0][m] = v.x;
            As[acol + 1][m] = v.y;
            As[acol + 2][m] = v.z;
            As[acol + 3][m] = v.w;
        }
#pragma unroll
        for (int r = 0; r < 2; r++) {
            int kk = brow + r * 8;
            *(float4*)&Bs[kk][bcol] =
                *(const float4*)&Bm[(size_t)(k0 + kk) * ND + n0 + bcol];
        }
        __syncthreads();
        micro_tile<132>(&As[0][0], &Bs[0][0], tx, ty, acc);
        __syncthreads();
    }

#pragma unroll
    for (int m = 0; m < 8; m++) {
        float* cp = C + (size_t)(m0 + ty * 8 + m) * ND + n0 + tx * 8;
        float4 o0 = make_float4(lo32(acc[m][0]), hi32(acc[m][0]),
                                lo32(acc[m][1]), hi32(acc[m][1]));
        float4 o1 = make_float4(lo32(acc[m][2]), hi32(acc[m][2]),
                                lo32(acc[m][3]), hi32(acc[m][3]));
        *(float4*)cp = o0;
        *(float4*)(cp + 4) = o1;
    }
}

// ---------------------------------------------------------------------------
// K2: Gram matrices G = A^T A, split-K over batch, upper-triangle tiles only
// ---------------------------------------------------------------------------
__global__ __launch_bounds__(256) void gram_gemm(const float* __restrict__ S,
                                                 const float* __restrict__ P) {
    const int TI_[10] = {0, 0, 0, 0, 1, 1, 1, 2, 2, 3};
    const int TJ_[10] = {0, 1, 2, 3, 1, 2, 3, 2, 3, 3};
    int pair = blockIdx.x;   // 0..9
    int sp = blockIdx.y;     // split
    int mat = blockIdx.z;    // 0: S, 1: P
    const float* A = mat ? P : S;
    float* C = g_gram[mat][sp];
    int i0 = TI_[pair] * 128, j0 = TJ_[pair] * 128;
    int kb = sp * KSPLIT;

    __shared__ __align__(16) float As[16][128];
    __shared__ __align__(16) float Bs[16][128];

    int t = threadIdx.x;
    int lrow = t >> 5;           // 0..7
    int lcol = (t & 31) << 2;    // 0..124
    int tx = t & 15, ty = t >> 4;

    unsigned long long acc[8][4];
#pragma unroll
    for (int i = 0; i < 8; i++)
#pragma unroll
        for (int j = 0; j < 4; j++) acc[i][j] = 0ull;

    for (int k0 = 0; k0 < KSPLIT; k0 += 16) {
#pragma unroll
        for (int r = 0; r < 2; r++) {
            int kk = lrow + r * 8;
            size_t goff = (size_t)(kb + k0 + kk) * ND;
            *(float4*)&As[kk][lcol] = *(const float4*)&A[goff + i0 + lcol];
            *(float4*)&Bs[kk][lcol] = *(const float4*)&A[goff + j0 + lcol];
        }
        __syncthreads();
        micro_tile<128>(&As[0][0], &Bs[0][0], tx, ty, acc);
        __syncthreads();
    }

#pragma unroll
    for (int m = 0; m < 8; m++) {
        float* cp = C + (size_t)(i0 + ty * 8 + m) * ND + j0 + tx * 8;
        float4 o0 = make_float4(lo32(acc[m][0]), hi32(acc[m][0]),
                                lo32(acc[m][1]), hi32(acc[m][1]));
        float4 o1 = make_float4(lo32(acc[m][2]), hi32(acc[m][2]),
                                lo32(acc[m][3]), hi32(acc[m][3]));
        *(float4*)cp = o0;
        *(float4*)(cp + 4) = o1;
    }
}

// ---------------------------------------------------------------------------
// K3: rec LN -> relu(stim + rec_norm) -> final LN. One block per row.
// ---------------------------------------------------------------------------
__device__ __forceinline__ float2 block_sum2(float2 v, float2* sbuf) {
#pragma unroll
    for (int o = 16; o > 0; o >>= 1) {
        v.x += __shfl_xor_sync(0xffffffffu, v.x, o);
        v.y += __shfl_xor_sync(0xffffffffu, v.y, o);
    }
    int w = threadIdx.x >> 5, l = threadIdx.x & 31;
    if (l == 0) sbuf[w] = v;
    __syncthreads();
    float2 r = make_float2(0.f, 0.f);
#pragma unroll
    for (int i = 0; i < 8; i++) {
        r.x += sbuf[i].x;
        r.y += sbuf[i].y;
    }
    __syncthreads();
    return r;
}

__global__ __launch_bounds__(256) void ln_kernel(float* __restrict__ out,
                                                 const float* __restrict__ rg,
                                                 const float* __restrict__ rb,
                                                 const float* __restrict__ ag,
                                                 const float* __restrict__ ab) {
    __shared__ float2 sbuf[8];
    size_t base = (size_t)blockIdx.x * ND;
    int t = threadIdx.x;

    float r0 = g_rec_out[base + t];
    float r1 = g_rec_out[base + t + 256];
    float2 s = block_sum2(make_float2(r0 + r1, r0 * r0 + r1 * r1), sbuf);
    float mu = s.x * (1.f / ND);
    float var = s.y * (1.f / ND) - mu * mu;
    float inv = rsqrtf(var + 1e-5f);
    float n0 = (r0 - mu) * inv * rg[t] + rb[t];
    float n1 = (r1 - mu) * inv * rg[t + 256] + rb[t + 256];

    float x0 = fmaxf(g_stim_out[base + t] + n0, 0.f);
    float x1 = fmaxf(g_stim_out[base + t + 256] + n1, 0.f);
    float2 s2 = block_sum2(make_float2(x0 + x1, x0 * x0 + x1 * x1), sbuf);
    float mu2 = s2.x * (1.f / ND);
    float var2 = s2.y * (1.f / ND) - mu2 * mu2;
    float inv2 = rsqrtf(var2 + 1e-5f);

    out[base + t] = (x0 - mu2) * inv2 * ag[t] + ab[t];
    out[base + t + 256] = (x1 - mu2) * inv2 * ag[t + 256] + ab[t + 256];
}

// ---------------------------------------------------------------------------
// K4: weight update. Per block: 8 rows. heb_row = G_row @ Wm (Wm L2-resident),
// then v = Wm*(1-decay_i) + heb*alpha, l2-row-normalize, write to out.
// ---------------------------------------------------------------------------
__global__ __launch_bounds__(256) void update_kernel(float* __restrict__ out_base,
                                                     const float* __restrict__ W,
                                                     const float* __restrict__ Wr,
                                                     const float* __restrict__ alpha,
                                                     const float* __restrict__ decay) {
    int z = blockIdx.x;        // 0..127
    int mat = z >> 6;
    int i0 = (z & 63) * 8;
    const float* Wm = mat ? Wr : W;
    float* o = out_base + (size_t)NB * ND + (size_t)mat * ND * ND;

    __shared__ float g[8][ND];   // 16 KB: G rows (partials summed, symmetry-expanded)
    __shared__ float sv[8][ND];  // 16 KB: updated rows before normalization
    __shared__ float norms[8];

    int t = threadIdx.x;
    for (int idx = t; idx < 8 * ND; idx += 256) {
        int r = idx >> 9, c = idx & 511;
        int i = i0 + r;
        int off = ((i >> 7) <= (c >> 7)) ? i * ND + c : c * ND + i;
        float s = 0.f;
#pragma unroll
        for (int sp = 0; sp < NSPLIT; sp++) s += g_gram[mat][sp][off];
        g[r][c] = s;
    }
    __syncthreads();

    float acc[8][2] = {};
    for (int k = 0; k < ND; k++) {
        float w0 = Wm[(size_t)k * ND + t];
        float w1 = Wm[(size_t)k * ND + t + 256];
#pragma unroll
        for (int r = 0; r < 8; r++) {
            float gk = g[r][k];
            acc[r][0] = fmaf(gk, w0, acc[r][0]);
            acc[r][1] = fmaf(gk, w1, acc[r][1]);
        }
    }

    float a0 = alpha[t], a1 = alpha[t + 256];
#pragma unroll
    for (int r = 0; r < 8; r++) {
        float dm = 1.f - decay[i0 + r];
        sv[r][t]       = Wm[(size_t)(i0 + r) * ND + t] * dm       + acc[r][0] * a0;
        sv[r][t + 256] = Wm[(size_t)(i0 + r) * ND + t + 256] * dm + acc[r][1] * a1;
    }
    __syncthreads();

    int w = t >> 5, l = t & 31;
    {
        float s = 0.f;
#pragma unroll
        for (int c = l; c < ND; c += 32) {
            float v = sv[w][c];
            s += v * v;
        }
#pragma unroll
        for (int o2 = 16; o2 > 0; o2 >>= 1) s += __shfl_xor_sync(0xffffffffu, s, o2);
        if (l == 0) norms[w] = fmaxf(sqrtf(s), 1e-12f);
    }
    __syncthreads();

#pragma unroll
    for (int r = 0; r < 8; r++) {
        float inv = 1.f / norms[r];
        o[(size_t)(i0 + r) * ND + t]       = sv[r][t] * inv;
        o[(size_t)(i0 + r) * ND + t + 256] = sv[r][t + 256] * inv;
    }
}

// ---------------------------------------------------------------------------
extern "C" void kernel_launch(void* const* d_in, const int* in_sizes, int n_in,
                              void* d_out, int out_size) {
    const float* S     = (const float*)d_in[0];
    const float* P     = (const float*)d_in[1];
    const float* W     = (const float*)d_in[2];
    const float* Wr    = (const float*)d_in[3];
    const float* alpha = (const float*)d_in[4];
    const float* decay = (const float*)d_in[5];
    const float* ag    = (const float*)d_in[6];
    const float* ab    = (const float*)d_in[7];
    const float* rg    = (const float*)d_in[8];
    const float* rb    = (const float*)d_in[9];
    float* out = (float*)d_out;

    fwd_gemm<<<dim3(ND / 128, NB / 128, 2), 256>>>(S, P, W, Wr);
    gram_gemm<<<dim3(10, NSPLIT, 2), 256>>>(S, P);
    ln_kernel<<<NB, 256>>>(out, rg, rb, ag, ab);
    if (out_size >= NB * ND + 2 * ND * ND)
        update_kernel<<<128, 256>>>(out, W, Wr, alpha, decay);
}

// round 3
// speedup vs baseline: 1.8725x; 1.8725x over previous
#include <cuda_runtime.h>
#include <cuda_bf16.h>
#include <cstdint>

#define NB 32768
#define ND 512
#define NSPLIT_G 16
#define KSPLIT_G (NB / NSPLIT_G)   // 2048

// ---------------------------------------------------------------------------
// Scratch (device globals: no allocation allowed)
// ---------------------------------------------------------------------------
__device__ float g_stim[(size_t)NB * ND];                    // 64 MB
__device__ float g_rec[(size_t)NB * ND];                     // 64 MB
__device__ __nv_bfloat16 g_s_split[2][(size_t)NB * 1024];    // 128 MB  [b][hi|lo]
__device__ __nv_bfloat16 g_st_split[2][(size_t)ND * 2 * NB]; // 128 MB  [i][hi|lo over b]
__device__ __nv_bfloat16 g_wt_split[2][(size_t)ND * 1024];   // 2 MB    Wt[n][hi|lo over k]
__device__ float g_gram[2][NSPLIT_G][ND * ND];               // 32 MB   split-K partials

// ---------------------------------------------------------------------------
// PTX helpers (sm_80+ compatible: cp.async, ldmatrix, mma.sync bf16)
// ---------------------------------------------------------------------------
__device__ __forceinline__ uint32_t smem_to_u32(const void* p) {
    uint32_t a;
    asm("{ .reg .u64 t; cvta.to.shared.u64 t, %1; cvt.u32.u64 %0, t; }"
        : "=r"(a) : "l"(p));
    return a;
}

#define CP16(dst, src) \
    asm volatile("cp.async.cg.shared.global [%0], [%1], 16;" :: "r"(dst), "l"(src))
#define CP_COMMIT() asm volatile("cp.async.commit_group;")
#define CP_WAIT0() asm volatile("cp.async.wait_group 0;")
#define CP_WAIT1() asm volatile("cp.async.wait_group 1;")

__device__ __forceinline__ void ldsm4(uint32_t* r, uint32_t addr) {
    asm volatile("ldmatrix.sync.aligned.m8n8.x4.shared.b16 {%0,%1,%2,%3}, [%4];"
                 : "=r"(r[0]), "=r"(r[1]), "=r"(r[2]), "=r"(r[3]) : "r"(addr));
}

__device__ __forceinline__ void mma16816(float* d, const uint32_t* a, const uint32_t* b) {
    asm volatile(
        "mma.sync.aligned.m16n8k16.row.col.f32.bf16.bf16.f32 "
        "{%0,%1,%2,%3}, {%4,%5,%6,%7}, {%8,%9}, {%0,%1,%2,%3};"
        : "+f"(d[0]), "+f"(d[1]), "+f"(d[2]), "+f"(d[3])
        : "r"(a[0]), "r"(a[1]), "r"(a[2]), "r"(a[3]), "r"(b[0]), "r"(b[1]));
}

// smem tile: 128 rows x 32 bf16 (64B), padded stride 80B (conflict-free ldmatrix)
#define TROWB 80
#define TILEB (128 * TROWB)   // 10240 B

// load one 128x32 bf16 tile (A and B) via cp.async; 4 x 16B per thread
__device__ __forceinline__ void load_tile(uint32_t smA, uint32_t smB,
                                          const __nv_bfloat16* Ap, size_t sA,
                                          const __nv_bfloat16* Bp, size_t sB, int t) {
#pragma unroll
    for (int r = 0; r < 2; r++) {
        int c = t + r * 256;
        int row = c >> 2, ch = c & 3;
        CP16(smA + row * TROWB + ch * 16, Ap + (size_t)row * sA + ch * 8);
        CP16(smB + row * TROWB + ch * 16, Bp + (size_t)row * sB + ch * 8);
    }
}

// per-thread ldmatrix offsets (byte offsets within a tile buffer)
struct LaneOff {
    uint32_t a[2];   // mt = 0,1
    uint32_t b[4];   // nt pairs 0..3
};
__device__ __forceinline__ LaneOff make_offsets(int t) {
    int w = t >> 5, l = t & 31;
    int wm = w & 3, wn = w >> 2;
    int mat = l >> 3, lrow = l & 7;
    LaneOff o;
#pragma unroll
    for (int mt = 0; mt < 2; mt++) {
        int m = wm * 32 + mt * 16 + (mat & 1) * 8 + lrow;
        int k = (mat >> 1) * 8;
        o.a[mt] = m * TROWB + k * 2;
    }
#pragma unroll
    for (int q = 0; q < 4; q++) {
        int n = wn * 64 + q * 16 + (l >> 4) * 8 + lrow;
        int k = ((l >> 3) & 1) * 8;
        o.b[q] = n * TROWB + k * 2;
    }
    return o;
}

// one BK=32 compute step on a resident tile pair
__device__ __forceinline__ void compute_tile(uint32_t smA, uint32_t smB,
                                             const LaneOff& o, float acc[2][8][4]) {
#pragma unroll
    for (int ks = 0; ks < 2; ks++) {
        uint32_t a[2][4], b[4][4];
        ldsm4(a[0], smA + o.a[0] + ks * 32);
        ldsm4(a[1], smA + o.a[1] + ks * 32);
#pragma unroll
        for (int q = 0; q < 4; q++) ldsm4(b[q], smB + o.b[q] + ks * 32);
#pragma unroll
        for (int mt = 0; mt < 2; mt++)
#pragma unroll
            for (int nt = 0; nt < 8; nt++)
                mma16816(acc[mt][nt], a[mt], &b[nt >> 1][(nt & 1) * 2]);
    }
}

// ---------------------------------------------------------------------------
// P1: W/Wr -> transposed bf16 split  Wt[n][k] (k: 0..511 hi, 512..1023 lo)
// ---------------------------------------------------------------------------
__global__ void wsplit_kernel(const float* __restrict__ W, const float* __restrict__ Wr) {
    __shared__ float tile[32][33];
    int mat = blockIdx.z;
    const float* src = mat ? Wr : W;
    __nv_bfloat16* dst = g_wt_split[mat];
    int k0 = blockIdx.x * 32, n0 = blockIdx.y * 32;
    int tx = threadIdx.x, ty = threadIdx.y;
    for (int ry = ty; ry < 32; ry += 8)
        tile[ry][tx] = src[(size_t)(k0 + ry) * ND + n0 + tx];
    __syncthreads();
    for (int ry = ty; ry < 32; ry += 8) {
        float v = tile[tx][ry];
        __nv_bfloat16 hi = __float2bfloat16(v);
        __nv_bfloat16 lo = __float2bfloat16(v - __bfloat162float(hi));
        dst[(size_t)(n0 + ry) * 1024 + k0 + tx] = hi;
        dst[(size_t)(n0 + ry) * 1024 + 512 + k0 + tx] = lo;
    }
}

// ---------------------------------------------------------------------------
// P2: S/P -> row-major bf16 split [b][1024] and transposed split [i][hi|lo over b]
// ---------------------------------------------------------------------------
__global__ __launch_bounds__(256) void ssplit_kernel(const float* __restrict__ S,
                                                     const float* __restrict__ P) {
    __shared__ float tile[128][33];
    int mat = blockIdx.z;
    const float* src = mat ? P : S;
    __nv_bfloat16* drow = g_s_split[mat];
    __nv_bfloat16* dcol = g_st_split[mat];
    int b0 = blockIdx.x * 128, c0 = blockIdx.y * 32;
    int t = threadIdx.x;
#pragma unroll
    for (int j = 0; j < 16; j++) {
        int idx = t + 256 * j;
        int r = idx >> 5, c = idx & 31;
        tile[r][c] = src[(size_t)(b0 + r) * ND + c0 + c];
    }
    __syncthreads();
#pragma unroll
    for (int j = 0; j < 16; j++) {
        int idx = t + 256 * j;
        int r = idx >> 5, c = idx & 31;
        float v = tile[r][c];
        __nv_bfloat16 hi = __float2bfloat16(v);
        __nv_bfloat16 lo = __float2bfloat16(v - __bfloat162float(hi));
        drow[(size_t)(b0 + r) * 1024 + c0 + c] = hi;
        drow[(size_t)(b0 + r) * 1024 + 512 + c0 + c] = lo;
    }
#pragma unroll
    for (int j = 0; j < 16; j++) {
        int idx = t + 256 * j;
        int il = idx >> 7, bl = idx & 127;
        float v = tile[bl][il];
        __nv_bfloat16 hi = __float2bfloat16(v);
        __nv_bfloat16 lo = __float2bfloat16(v - __bfloat162float(hi));
        size_t rb = (size_t)(c0 + il) * (2 * NB);
        dcol[rb + b0 + bl] = hi;
        dcol[rb + NB + b0 + bl] = lo;
    }
}

// ---------------------------------------------------------------------------
// K1: fwd GEMM (bf16 split, 3 combos): C[m,n] = A[m,k] * Wt[n,k]^T
// ---------------------------------------------------------------------------
#define FWD_NITER 48

__global__ __launch_bounds__(256) void fwd_mma() {
    __shared__ __align__(128) char sm[2][2 * TILEB];
    int t = threadIdx.x;
    int mat = blockIdx.z;
    int m0 = blockIdx.x * 128, n0 = blockIdx.y * 128;
    const __nv_bfloat16* Ag = g_s_split[mat];
    const __nv_bfloat16* Bg = g_wt_split[mat];
    float* C = mat ? g_rec : g_stim;

    uint32_t smb[2][2];
    smb[0][0] = smem_to_u32(&sm[0][0]);
    smb[0][1] = smb[0][0] + TILEB;
    smb[1][0] = smem_to_u32(&sm[1][0]);
    smb[1][1] = smb[1][0] + TILEB;

    LaneOff o = make_offsets(t);
    float acc[2][8][4];
#pragma unroll
    for (int i = 0; i < 2; i++)
#pragma unroll
        for (int j = 0; j < 8; j++)
#pragma unroll
            for (int q = 0; q < 4; q++) acc[i][j][q] = 0.f;

    auto tile_ptrs = [&](int i, const __nv_bfloat16*& Ap, const __nv_bfloat16*& Bp) {
        int combo = i >> 4, c = i & 15;
        int ka = ((combo == 2) ? 512 : 0) + c * 32;
        int kb = ((combo == 1) ? 512 : 0) + c * 32;
        Ap = Ag + (size_t)m0 * 1024 + ka;
        Bp = Bg + (size_t)n0 * 1024 + kb;
    };

    {
        const __nv_bfloat16 *Ap, *Bp;
        tile_ptrs(0, Ap, Bp);
        load_tile(smb[0][0], smb[0][1], Ap, 1024, Bp, 1024, t);
        CP_COMMIT();
    }
    for (int i = 0; i < FWD_NITER; i++) {
        int buf = i & 1;
        if (i + 1 < FWD_NITER) {
            const __nv_bfloat16 *Ap, *Bp;
            tile_ptrs(i + 1, Ap, Bp);
            load_tile(smb[buf ^ 1][0], smb[buf ^ 1][1], Ap, 1024, Bp, 1024, t);
            CP_COMMIT();
            CP_WAIT1();
        } else {
            CP_WAIT0();
        }
        __syncthreads();
        compute_tile(smb[buf][0], smb[buf][1], o, acc);
        __syncthreads();
    }

    int w = t >> 5, l = t & 31;
    int wm = w & 3, wn = w >> 2;
#pragma unroll
    for (int mt = 0; mt < 2; mt++)
#pragma unroll
        for (int nt = 0; nt < 8; nt++) {
            int m = m0 + wm * 32 + mt * 16 + (l >> 2);
            int n = n0 + wn * 64 + nt * 8 + (l & 3) * 2;
            *(float2*)&C[(size_t)m * ND + n] = make_float2(acc[mt][nt][0], acc[mt][nt][1]);
            *(float2*)&C[(size_t)(m + 8) * ND + n] = make_float2(acc[mt][nt][2], acc[mt][nt][3]);
        }
}

// ---------------------------------------------------------------------------
// K2: Gram GEMM (bf16 split, 3 combos): G = A^T A, 10 upper tiles, split-K
// ---------------------------------------------------------------------------
#define GRAM_NITER (3 * (KSPLIT_G / 32))   // 192

__global__ __launch_bounds__(256) void gram_mma() {
    __shared__ __align__(128) char sm[2][2 * TILEB];
    const int TI_[10] = {0, 0, 0, 0, 1, 1, 1, 2, 2, 3};
    const int TJ_[10] = {0, 1, 2, 3, 1, 2, 3, 2, 3, 3};
    int t = threadIdx.x;
    int mat = blockIdx.z;
    int sp = blockIdx.y;
    int i0 = TI_[blockIdx.x] * 128, j0 = TJ_[blockIdx.x] * 128;
    const __nv_bfloat16* Sg = g_st_split[mat];

    uint32_t smb[2][2];
    smb[0][0] = smem_to_u32(&sm[0][0]);
    smb[0][1] = smb[0][0] + TILEB;
    smb[1][0] = smem_to_u32(&sm[1][0]);
    smb[1][1] = smb[1][0] + TILEB;

    LaneOff o = make_offsets(t);
    float acc[2][8][4];
#pragma unroll
    for (int i = 0; i < 2; i++)
#pragma unroll
        for (int j = 0; j < 8; j++)
#pragma unroll
            for (int q = 0; q < 4; q++) acc[i][j][q] = 0.f;

    const int NC = KSPLIT_G / 32;  // 64
    auto tile_ptrs = [&](int i, const __nv_bfloat16*& Ap, const __nv_bfloat16*& Bp) {
        int combo = i / NC, c = i % NC;
        size_t ka = (size_t)((combo == 2) ? NB : 0) + (size_t)sp * KSPLIT_G + c * 32;
        size_t kb = (size_t)((combo == 1) ? NB : 0) + (size_t)sp * KSPLIT_G + c * 32;
        Ap = Sg + (size_t)i0 * (2 * NB) + ka;
        Bp = Sg + (size_t)j0 * (2 * NB) + kb;
    };

    {
        const __nv_bfloat16 *Ap, *Bp;
        tile_ptrs(0, Ap, Bp);
        load_tile(smb[0][0], smb[0][1], Ap, 2 * NB, Bp, 2 * NB, t);
        CP_COMMIT();
    }
    for (int i = 0; i < GRAM_NITER; i++) {
        int buf = i & 1;
        if (i + 1 < GRAM_NITER) {
            const __nv_bfloat16 *Ap, *Bp;
            tile_ptrs(i + 1, Ap, Bp);
            load_tile(smb[buf ^ 1][0], smb[buf ^ 1][1], Ap, 2 * NB, Bp, 2 * NB, t);
            CP_COMMIT();
            CP_WAIT1();
        } else {
            CP_WAIT0();
        }
        __syncthreads();
        compute_tile(smb[buf][0], smb[buf][1], o, acc);
        __syncthreads();
    }

    float* G = g_gram[mat][sp];
    int w = t >> 5, l = t & 31;
    int wm = w & 3, wn = w >> 2;
#pragma unroll
    for (int mt = 0; mt < 2; mt++)
#pragma unroll
        for (int nt = 0; nt < 8; nt++) {
            int m = i0 + wm * 32 + mt * 16 + (l >> 2);
            int n = j0 + wn * 64 + nt * 8 + (l & 3) * 2;
            *(float2*)&G[(size_t)m * ND + n] = make_float2(acc[mt][nt][0], acc[mt][nt][1]);
            *(float2*)&G[(size_t)(m + 8) * ND + n] = make_float2(acc[mt][nt][2], acc[mt][nt][3]);
        }
}

// ---------------------------------------------------------------------------
// K3: rec LN -> relu(stim + rec_norm) -> final LN. One block per row.
// ---------------------------------------------------------------------------
__device__ __forceinline__ float2 block_sum2(float2 v, float2* sbuf) {
#pragma unroll
    for (int o = 16; o > 0; o >>= 1) {
        v.x += __shfl_xor_sync(0xffffffffu, v.x, o);
        v.y += __shfl_xor_sync(0xffffffffu, v.y, o);
    }
    int w = threadIdx.x >> 5, l = threadIdx.x & 31;
    if (l == 0) sbuf[w] = v;
    __syncthreads();
    float2 r = make_float2(0.f, 0.f);
#pragma unroll
    for (int i = 0; i < 8; i++) {
        r.x += sbuf[i].x;
        r.y += sbuf[i].y;
    }
    __syncthreads();
    return r;
}

__global__ __launch_bounds__(256) void ln_kernel(float* __restrict__ out,
                                                 const float* __restrict__ rg,
                                                 const float* __restrict__ rb,
                                                 const float* __restrict__ ag,
                                                 const float* __restrict__ ab) {
    __shared__ float2 sbuf[8];
    size_t base = (size_t)blockIdx.x * ND;
    int t = threadIdx.x;

    float r0 = g_rec[base + t];
    float r1 = g_rec[base + t + 256];
    float2 s = block_sum2(make_float2(r0 + r1, r0 * r0 + r1 * r1), sbuf);
    float mu = s.x * (1.f / ND);
    float var = s.y * (1.f / ND) - mu * mu;
    float inv = rsqrtf(var + 1e-5f);
    float n0 = (r0 - mu) * inv * rg[t] + rb[t];
    float n1 = (r1 - mu) * inv * rg[t + 256] + rb[t + 256];

    float x0 = fmaxf(g_stim[base + t] + n0, 0.f);
    float x1 = fmaxf(g_stim[base + t + 256] + n1, 0.f);
    float2 s2 = block_sum2(make_float2(x0 + x1, x0 * x0 + x1 * x1), sbuf);
    float mu2 = s2.x * (1.f / ND);
    float var2 = s2.y * (1.f / ND) - mu2 * mu2;
    float inv2 = rsqrtf(var2 + 1e-5f);

    out[base + t] = (x0 - mu2) * inv2 * ag[t] + ab[t];
    out[base + t + 256] = (x1 - mu2) * inv2 * ag[t + 256] + ab[t + 256];
}

// ---------------------------------------------------------------------------
// K4: weight update: sum gram splits (mirror lower tiles), heb = G @ Wm,
//     scale, l2-normalize rows
// ---------------------------------------------------------------------------
__global__ __launch_bounds__(256) void update_kernel(float* __restrict__ out_base,
                                                     const float* __restrict__ W,
                                                     const float* __restrict__ Wr,
                                                     const float* __restrict__ alpha,
                                                     const float* __restrict__ decay) {
    int z = blockIdx.x;        // 0..127
    int mat = z >> 6;
    int i0 = (z & 63) * 8;
    const float* Wm = mat ? Wr : W;
    float* o = out_base + (size_t)NB * ND + (size_t)mat * ND * ND;

    __shared__ float g[8][ND];
    __shared__ float sv[8][ND];
    __shared__ float norms[8];

    int t = threadIdx.x;
    for (int idx = t; idx < 8 * ND; idx += 256) {
        int r = idx >> 9, c = idx & 511;
        int i = i0 + r;
        size_t off = ((i >> 7) <= (c >> 7)) ? (size_t)i * ND + c : (size_t)c * ND + i;
        float s = 0.f;
#pragma unroll
        for (int sp = 0; sp < NSPLIT_G; sp++) s += g_gram[mat][sp][off];
        g[r][c] = s;
    }
    __syncthreads();

    float acc[8][2] = {};
    for (int k0 = 0; k0 < ND; k0 += 8) {
        float w0[8], w1[8];
#pragma unroll
        for (int u = 0; u < 8; u++) {
            w0[u] = Wm[(size_t)(k0 + u) * ND + t];
            w1[u] = Wm[(size_t)(k0 + u) * ND + t + 256];
        }
#pragma unroll
        for (int u = 0; u < 8; u++) {
#pragma unroll
            for (int r = 0; r < 8; r++) {
                float gk = g[r][k0 + u];
                acc[r][0] = fmaf(gk, w0[u], acc[r][0]);
                acc[r][1] = fmaf(gk, w1[u], acc[r][1]);
            }
        }
    }

    float a0 = alpha[t], a1 = alpha[t + 256];
#pragma unroll
    for (int r = 0; r < 8; r++) {
        float dm = 1.f - decay[i0 + r];
        sv[r][t]       = Wm[(size_t)(i0 + r) * ND + t] * dm       + acc[r][0] * a0;
        sv[r][t + 256] = Wm[(size_t)(i0 + r) * ND + t + 256] * dm + acc[r][1] * a1;
    }
    __syncthreads();

    int w = t >> 5, l = t & 31;
    {
        float s = 0.f;
#pragma unroll
        for (int c = l; c < ND; c += 32) {
            float v = sv[w][c];
            s += v * v;
        }
#pragma unroll
        for (int o2 = 16; o2 > 0; o2 >>= 1) s += __shfl_xor_sync(0xffffffffu, s, o2);
        if (l == 0) norms[w] = fmaxf(sqrtf(s), 1e-12f);
    }
    __syncthreads();

#pragma unroll
    for (int r = 0; r < 8; r++) {
        float inv = 1.f / norms[r];
        o[(size_t)(i0 + r) * ND + t]       = sv[r][t] * inv;
        o[(size_t)(i0 + r) * ND + t + 256] = sv[r][t + 256] * inv;
    }
}

// ---------------------------------------------------------------------------
extern "C" void kernel_launch(void* const* d_in, const int* in_sizes, int n_in,
                              void* d_out, int out_size) {
    const float* S     = (const float*)d_in[0];
    const float* P     = (const float*)d_in[1];
    const float* W     = (const float*)d_in[2];
    const float* Wr    = (const float*)d_in[3];
    const float* alpha = (const float*)d_in[4];
    const float* decay = (const float*)d_in[5];
    const float* ag    = (const float*)d_in[6];
    const float* ab    = (const float*)d_in[7];
    const float* rg    = (const float*)d_in[8];
    const float* rb    = (const float*)d_in[9];
    float* out = (float*)d_out;

    wsplit_kernel<<<dim3(16, 16, 2), dim3(32, 8)>>>(W, Wr);
    ssplit_kernel<<<dim3(NB / 128, ND / 32, 2), 256>>>(S, P);
    fwd_mma<<<dim3(NB / 128, ND / 128, 2), 256>>>();
    gram_mma<<<dim3(10, NSPLIT_G, 2), 256>>>();
    ln_kernel<<<NB, 256>>>(out, rg, rb, ag, ab);
    update_kernel<<<128, 256>>>(out, W, Wr, alpha, decay);
}

// round 4
// speedup vs baseline: 2.1731x; 1.1605x over previous
#include <cuda_runtime.h>
#include <cuda_bf16.h>
#include <cstdint>

#define NB 32768
#define ND 512
#define NSPLIT_G 16
#define KSPLIT_G (NB / NSPLIT_G)   // 2048

// ---------------------------------------------------------------------------
// Scratch (device globals: no allocation allowed)
// ---------------------------------------------------------------------------
__device__ float g_stim[(size_t)NB * ND];                    // 64 MB
__device__ float g_rec[(size_t)NB * ND];                     // 64 MB
__device__ __nv_bfloat16 g_s_split[2][(size_t)NB * 1024];    // 128 MB  [b][hi|lo]
__device__ __nv_bfloat16 g_st_split[2][(size_t)ND * 2 * NB]; // 128 MB  [i][hi|lo over b]
__device__ __nv_bfloat16 g_wt_split[2][(size_t)ND * 1024];   // 2 MB    Wt[n][hi|lo over k]
__device__ float g_gram[2][NSPLIT_G][ND * ND];               // 32 MB   split-K partials

// ---------------------------------------------------------------------------
// PTX helpers (sm_80+ compatible: cp.async, ldmatrix, mma.sync bf16)
// ---------------------------------------------------------------------------
__device__ __forceinline__ uint32_t smem_to_u32(const void* p) {
    uint32_t a;
    asm("{ .reg .u64 t; cvta.to.shared.u64 t, %1; cvt.u32.u64 %0, t; }"
        : "=r"(a) : "l"(p));
    return a;
}

#define CP16(dst, src) \
    asm volatile("cp.async.cg.shared.global [%0], [%1], 16;" :: "r"(dst), "l"(src))
#define CP_COMMIT() asm volatile("cp.async.commit_group;")
#define CP_WAIT0() asm volatile("cp.async.wait_group 0;")
#define CP_WAIT1() asm volatile("cp.async.wait_group 1;")

__device__ __forceinline__ void ldsm4(uint32_t* r, uint32_t addr) {
    asm volatile("ldmatrix.sync.aligned.m8n8.x4.shared.b16 {%0,%1,%2,%3}, [%4];"
                 : "=r"(r[0]), "=r"(r[1]), "=r"(r[2]), "=r"(r[3]) : "r"(addr));
}

__device__ __forceinline__ void mma16816(float* d, const uint32_t* a, const uint32_t* b) {
    asm volatile(
        "mma.sync.aligned.m16n8k16.row.col.f32.bf16.bf16.f32 "
        "{%0,%1,%2,%3}, {%4,%5,%6,%7}, {%8,%9}, {%0,%1,%2,%3};"
        : "+f"(d[0]), "+f"(d[1]), "+f"(d[2]), "+f"(d[3])
        : "r"(a[0]), "r"(a[1]), "r"(a[2]), "r"(a[3]), "r"(b[0]), "r"(b[1]));
}

// smem tile: 128 rows x 32 bf16 (64B), padded stride 80B (conflict-free ldmatrix)
#define TROWB 80
#define TILEB (128 * TROWB)        // 10240 B
#define STAGEB (4 * TILEB)         // Ahi|Alo|Bhi|Blo = 40960 B
#define PIPE_SMEM (2 * STAGEB)     // 81920 B dynamic

// load one stage: 4 tiles (Ahi, Alo, Bhi, Blo), 128x32 bf16 each, via cp.async
__device__ __forceinline__ void load_stage(uint32_t sm,
                                           const __nv_bfloat16* Ahi,
                                           const __nv_bfloat16* Alo, size_t sA,
                                           const __nv_bfloat16* Bhi,
                                           const __nv_bfloat16* Blo, size_t sB, int t) {
#pragma unroll
    for (int r = 0; r < 2; r++) {
        int c = t + r * 256;
        int row = c >> 2, ch = c & 3;
        uint32_t d = row * TROWB + ch * 16;
        size_t ga = (size_t)row * sA + ch * 8;
        size_t gb = (size_t)row * sB + ch * 8;
        CP16(sm + d, Ahi + ga);
        CP16(sm + TILEB + d, Alo + ga);
        CP16(sm + 2 * TILEB + d, Bhi + gb);
        CP16(sm + 3 * TILEB + d, Blo + gb);
    }
}

// per-thread ldmatrix offsets (byte offsets within a tile buffer)
struct LaneOff {
    uint32_t a[2];   // mt = 0,1
    uint32_t b[4];   // nt pairs 0..3
};
__device__ __forceinline__ LaneOff make_offsets(int t) {
    int w = t >> 5, l = t & 31;
    int wm = w & 3, wn = w >> 2;
    int mat = l >> 3, lrow = l & 7;
    LaneOff o;
#pragma unroll
    for (int mt = 0; mt < 2; mt++) {
        int m = wm * 32 + mt * 16 + (mat & 1) * 8 + lrow;
        int k = (mat >> 1) * 8;
        o.a[mt] = m * TROWB + k * 2;
    }
#pragma unroll
    for (int q = 0; q < 4; q++) {
        int n = wn * 64 + q * 16 + (l >> 4) * 8 + lrow;
        int k = ((l >> 3) & 1) * 8;
        o.b[q] = n * TROWB + k * 2;
    }
    return o;
}

// one combo pass (BK=32) over resident A/B tiles
__device__ __forceinline__ void compute_pass(uint32_t smA, uint32_t smB,
                                             const LaneOff& o, float acc[2][8][4]) {
#pragma unroll
    for (int ks = 0; ks < 2; ks++) {
        uint32_t a[2][4], b[4][4];
        ldsm4(a[0], smA + o.a[0] + ks * 32);
        ldsm4(a[1], smA + o.a[1] + ks * 32);
#pragma unroll
        for (int q = 0; q < 4; q++) ldsm4(b[q], smB + o.b[q] + ks * 32);
#pragma unroll
        for (int mt = 0; mt < 2; mt++)
#pragma unroll
            for (int nt = 0; nt < 8; nt++)
                mma16816(acc[mt][nt], a[mt], &b[nt >> 1][(nt & 1) * 2]);
    }
}

// all 3 split combos on one resident stage: hi*hi + hi*lo + lo*hi
__device__ __forceinline__ void compute_stage(uint32_t sm, const LaneOff& o,
                                              float acc[2][8][4]) {
    compute_pass(sm, sm + 2 * TILEB, o, acc);              // Ahi * Bhi
    compute_pass(sm, sm + 3 * TILEB, o, acc);              // Ahi * Blo
    compute_pass(sm + TILEB, sm + 2 * TILEB, o, acc);      // Alo * Bhi
}

// ---------------------------------------------------------------------------
// P1: W/Wr -> transposed bf16 split  Wt[n][k] (k: 0..511 hi, 512..1023 lo)
// ---------------------------------------------------------------------------
__global__ void wsplit_kernel(const float* __restrict__ W, const float* __restrict__ Wr) {
    __shared__ float tile[32][33];
    int mat = blockIdx.z;
    const float* src = mat ? Wr : W;
    __nv_bfloat16* dst = g_wt_split[mat];
    int k0 = blockIdx.x * 32, n0 = blockIdx.y * 32;
    int tx = threadIdx.x, ty = threadIdx.y;
    for (int ry = ty; ry < 32; ry += 8)
        tile[ry][tx] = src[(size_t)(k0 + ry) * ND + n0 + tx];
    __syncthreads();
    for (int ry = ty; ry < 32; ry += 8) {
        float v = tile[tx][ry];
        __nv_bfloat16 hi = __float2bfloat16(v);
        __nv_bfloat16 lo = __float2bfloat16(v - __bfloat162float(hi));
        dst[(size_t)(n0 + ry) * 1024 + k0 + tx] = hi;
        dst[(size_t)(n0 + ry) * 1024 + 512 + k0 + tx] = lo;
    }
}

// ---------------------------------------------------------------------------
// P2: S/P -> row-major bf16 split [b][1024] and transposed split [i][hi|lo over b]
// ---------------------------------------------------------------------------
__global__ __launch_bounds__(256) void ssplit_kernel(const float* __restrict__ S,
                                                     const float* __restrict__ P) {
    __shared__ float tile[128][33];
    int mat = blockIdx.z;
    const float* src = mat ? P : S;
    __nv_bfloat16* drow = g_s_split[mat];
    __nv_bfloat16* dcol = g_st_split[mat];
    int b0 = blockIdx.x * 128, c0 = blockIdx.y * 32;
    int t = threadIdx.x;
#pragma unroll
    for (int j = 0; j < 16; j++) {
        int idx = t + 256 * j;
        int r = idx >> 5, c = idx & 31;
        tile[r][c] = src[(size_t)(b0 + r) * ND + c0 + c];
    }
    __syncthreads();
#pragma unroll
    for (int j = 0; j < 16; j++) {
        int idx = t + 256 * j;
        int r = idx >> 5, c = idx & 31;
        float v = tile[r][c];
        __nv_bfloat16 hi = __float2bfloat16(v);
        __nv_bfloat16 lo = __float2bfloat16(v - __bfloat162float(hi));
        drow[(size_t)(b0 + r) * 1024 + c0 + c] = hi;
        drow[(size_t)(b0 + r) * 1024 + 512 + c0 + c] = lo;
    }
#pragma unroll
    for (int j = 0; j < 16; j++) {
        int idx = t + 256 * j;
        int il = idx >> 7, bl = idx & 127;
        float v = tile[bl][il];
        __nv_bfloat16 hi = __float2bfloat16(v);
        __nv_bfloat16 lo = __float2bfloat16(v - __bfloat162float(hi));
        size_t rb = (size_t)(c0 + il) * (2 * NB);
        dcol[rb + b0 + bl] = hi;
        dcol[rb + NB + b0 + bl] = lo;
    }
}

// ---------------------------------------------------------------------------
// K1: fwd GEMM (bf16 split): C[m,n] = A[m,k] * Wt[n,k]^T.
//     blockIdx.x = n-block (4) so a wave shares A panels via L2.
// ---------------------------------------------------------------------------
#define FWD_NST 16

__global__ __launch_bounds__(256, 2) void fwd_mma() {
    extern __shared__ __align__(128) char dynsm[];
    int t = threadIdx.x;
    int mat = blockIdx.z;
    int n0 = blockIdx.x * 128, m0 = blockIdx.y * 128;
    const __nv_bfloat16* Ag = g_s_split[mat];
    const __nv_bfloat16* Bg = g_wt_split[mat];
    float* C = mat ? g_rec : g_stim;

    uint32_t smb[2] = {smem_to_u32(dynsm), smem_to_u32(dynsm) + STAGEB};
    LaneOff o = make_offsets(t);
    float acc[2][8][4];
#pragma unroll
    for (int i = 0; i < 2; i++)
#pragma unroll
        for (int j = 0; j < 8; j++)
#pragma unroll
            for (int q = 0; q < 4; q++) acc[i][j][q] = 0.f;

    auto issue = [&](int i, int buf) {
        const __nv_bfloat16* Ab = Ag + (size_t)m0 * 1024 + i * 32;
        const __nv_bfloat16* Bb = Bg + (size_t)n0 * 1024 + i * 32;
        load_stage(smb[buf], Ab, Ab + 512, 1024, Bb, Bb + 512, 1024, t);
        CP_COMMIT();
    };

    issue(0, 0);
    for (int i = 0; i < FWD_NST; i++) {
        int buf = i & 1;
        if (i + 1 < FWD_NST) {
            issue(i + 1, buf ^ 1);
            CP_WAIT1();
        } else {
            CP_WAIT0();
        }
        __syncthreads();
        compute_stage(smb[buf], o, acc);
        __syncthreads();
    }

    int w = t >> 5, l = t & 31;
    int wm = w & 3, wn = w >> 2;
#pragma unroll
    for (int mt = 0; mt < 2; mt++)
#pragma unroll
        for (int nt = 0; nt < 8; nt++) {
            int m = m0 + wm * 32 + mt * 16 + (l >> 2);
            int n = n0 + wn * 64 + nt * 8 + (l & 3) * 2;
            *(float2*)&C[(size_t)m * ND + n] = make_float2(acc[mt][nt][0], acc[mt][nt][1]);
            *(float2*)&C[(size_t)(m + 8) * ND + n] = make_float2(acc[mt][nt][2], acc[mt][nt][3]);
        }
}

// ---------------------------------------------------------------------------
// K2: Gram GEMM (bf16 split): G = A^T A, 10 upper tiles, split-K over batch
// ---------------------------------------------------------------------------
#define GRAM_NST (KSPLIT_G / 32)   // 64

__global__ __launch_bounds__(256, 2) void gram_mma() {
    extern __shared__ __align__(128) char dynsm[];
    const int TI_[10] = {0, 0, 0, 0, 1, 1, 1, 2, 2, 3};
    const int TJ_[10] = {0, 1, 2, 3, 1, 2, 3, 2, 3, 3};
    int t = threadIdx.x;
    int mat = blockIdx.z;
    int sp = blockIdx.y;
    int i0 = TI_[blockIdx.x] * 128, j0 = TJ_[blockIdx.x] * 128;
    const __nv_bfloat16* Sg = g_st_split[mat];

    uint32_t smb[2] = {smem_to_u32(dynsm), smem_to_u32(dynsm) + STAGEB};
    LaneOff o = make_offsets(t);
    float acc[2][8][4];
#pragma unroll
    for (int i = 0; i < 2; i++)
#pragma unroll
        for (int j = 0; j < 8; j++)
#pragma unroll
            for (int q = 0; q < 4; q++) acc[i][j][q] = 0.f;

    auto issue = [&](int i, int buf) {
        size_t k = (size_t)sp * KSPLIT_G + i * 32;
        const __nv_bfloat16* Ab = Sg + (size_t)i0 * (2 * NB) + k;
        const __nv_bfloat16* Bb = Sg + (size_t)j0 * (2 * NB) + k;
        load_stage(smb[buf], Ab, Ab + NB, 2 * NB, Bb, Bb + NB, 2 * NB, t);
        CP_COMMIT();
    };

    issue(0, 0);
    for (int i = 0; i < GRAM_NST; i++) {
        int buf = i & 1;
        if (i + 1 < GRAM_NST) {
            issue(i + 1, buf ^ 1);
            CP_WAIT1();
        } else {
            CP_WAIT0();
        }
        __syncthreads();
        compute_stage(smb[buf], o, acc);
        __syncthreads();
    }

    float* G = g_gram[mat][sp];
    int w = t >> 5, l = t & 31;
    int wm = w & 3, wn = w >> 2;
#pragma unroll
    for (int mt = 0; mt < 2; mt++)
#pragma unroll
        for (int nt = 0; nt < 8; nt++) {
            int m = i0 + wm * 32 + mt * 16 + (l >> 2);
            int n = j0 + wn * 64 + nt * 8 + (l & 3) * 2;
            *(float2*)&G[(size_t)m * ND + n] = make_float2(acc[mt][nt][0], acc[mt][nt][1]);
            *(float2*)&G[(size_t)(m + 8) * ND + n] = make_float2(acc[mt][nt][2], acc[mt][nt][3]);
        }
}

// ---------------------------------------------------------------------------
// K3: rec LN -> relu(stim + rec_norm) -> final LN. One block per row.
// ---------------------------------------------------------------------------
__device__ __forceinline__ float2 block_sum2(float2 v, float2* sbuf) {
#pragma unroll
    for (int o = 16; o > 0; o >>= 1) {
        v.x += __shfl_xor_sync(0xffffffffu, v.x, o);
        v.y += __shfl_xor_sync(0xffffffffu, v.y, o);
    }
    int w = threadIdx.x >> 5, l = threadIdx.x & 31;
    if (l == 0) sbuf[w] = v;
    __syncthreads();
    float2 r = make_float2(0.f, 0.f);
#pragma unroll
    for (int i = 0; i < 8; i++) {
        r.x += sbuf[i].x;
        r.y += sbuf[i].y;
    }
    __syncthreads();
    return r;
}

__global__ __launch_bounds__(256) void ln_kernel(float* __restrict__ out,
                                                 const float* __restrict__ rg,
                                                 const float* __restrict__ rb,
                                                 const float* __restrict__ ag,
                                                 const float* __restrict__ ab) {
    __shared__ float2 sbuf[8];
    size_t base = (size_t)blockIdx.x * ND;
    int t = threadIdx.x;

    float r0 = g_rec[base + t];
    float r1 = g_rec[base + t + 256];
    float2 s = block_sum2(make_float2(r0 + r1, r0 * r0 + r1 * r1), sbuf);
    float mu = s.x * (1.f / ND);
    float var = s.y * (1.f / ND) - mu * mu;
    float inv = rsqrtf(var + 1e-5f);
    float n0 = (r0 - mu) * inv * rg[t] + rb[t];
    float n1 = (r1 - mu) * inv * rg[t + 256] + rb[t + 256];

    float x0 = fmaxf(g_stim[base + t] + n0, 0.f);
    float x1 = fmaxf(g_stim[base + t + 256] + n1, 0.f);
    float2 s2 = block_sum2(make_float2(x0 + x1, x0 * x0 + x1 * x1), sbuf);
    float mu2 = s2.x * (1.f / ND);
    float var2 = s2.y * (1.f / ND) - mu2 * mu2;
    float inv2 = rsqrtf(var2 + 1e-5f);

    out[base + t] = (x0 - mu2) * inv2 * ag[t] + ab[t];
    out[base + t + 256] = (x1 - mu2) * inv2 * ag[t + 256] + ab[t + 256];
}

// ---------------------------------------------------------------------------
// K4: weight update: sum gram splits (mirror lower tiles), heb = G @ Wm,
//     scale, l2-normalize rows
// ---------------------------------------------------------------------------
__global__ __launch_bounds__(256) void update_kernel(float* __restrict__ out_base,
                                                     const float* __restrict__ W,
                                                     const float* __restrict__ Wr,
                                                     const float* __restrict__ alpha,
                                                     const float* __restrict__ decay) {
    int z = blockIdx.x;        // 0..127
    int mat = z >> 6;
    int i0 = (z & 63) * 8;
    const float* Wm = mat ? Wr : W;
    float* o = out_base + (size_t)NB * ND + (size_t)mat * ND * ND;

    __shared__ float g[8][ND];
    __shared__ float sv[8][ND];
    __shared__ float norms[8];

    int t = threadIdx.x;
    for (int idx = t; idx < 8 * ND; idx += 256) {
        int r = idx >> 9, c = idx & 511;
        int i = i0 + r;
        size_t off = ((i >> 7) <= (c >> 7)) ? (size_t)i * ND + c : (size_t)c * ND + i;
        float s = 0.f;
#pragma unroll
        for (int sp = 0; sp < NSPLIT_G; sp++) s += g_gram[mat][sp][off];
        g[r][c] = s;
    }
    __syncthreads();

    float acc[8][2] = {};
    for (int k0 = 0; k0 < ND; k0 += 8) {
        float w0[8], w1[8];
#pragma unroll
        for (int u = 0; u < 8; u++) {
            w0[u] = Wm[(size_t)(k0 + u) * ND + t];
            w1[u] = Wm[(size_t)(k0 + u) * ND + t + 256];
        }
#pragma unroll
        for (int u = 0; u < 8; u++) {
#pragma unroll
            for (int r = 0; r < 8; r++) {
                float gk = g[r][k0 + u];
                acc[r][0] = fmaf(gk, w0[u], acc[r][0]);
                acc[r][1] = fmaf(gk, w1[u], acc[r][1]);
            }
        }
    }

    float a0 = alpha[t], a1 = alpha[t + 256];
#pragma unroll
    for (int r = 0; r < 8; r++) {
        float dm = 1.f - decay[i0 + r];
        sv[r][t]       = Wm[(size_t)(i0 + r) * ND + t] * dm       + acc[r][0] * a0;
        sv[r][t + 256] = Wm[(size_t)(i0 + r) * ND + t + 256] * dm + acc[r][1] * a1;
    }
    __syncthreads();

    int w = t >> 5, l = t & 31;
    {
        float s = 0.f;
#pragma unroll
        for (int c = l; c < ND; c += 32) {
            float v = sv[w][c];
            s += v * v;
        }
#pragma unroll
        for (int o2 = 16; o2 > 0; o2 >>= 1) s += __shfl_xor_sync(0xffffffffu, s, o2);
        if (l == 0) norms[w] = fmaxf(sqrtf(s), 1e-12f);
    }
    __syncthreads();

#pragma unroll
    for (int r = 0; r < 8; r++) {
        float inv = 1.f / norms[r];
        o[(size_t)(i0 + r) * ND + t]       = sv[r][t] * inv;
        o[(size_t)(i0 + r) * ND + t + 256] = sv[r][t + 256] * inv;
    }
}

// ---------------------------------------------------------------------------
extern "C" void kernel_launch(void* const* d_in, const int* in_sizes, int n_in,
                              void* d_out, int out_size) {
    const float* S     = (const float*)d_in[0];
    const float* P     = (const float*)d_in[1];
    const float* W     = (const float*)d_in[2];
    const float* Wr    = (const float*)d_in[3];
    const float* alpha = (const float*)d_in[4];
    const float* decay = (const float*)d_in[5];
    const float* ag    = (const float*)d_in[6];
    const float* ab    = (const float*)d_in[7];
    const float* rg    = (const float*)d_in[8];
    const float* rb    = (const float*)d_in[9];
    float* out = (float*)d_out;

    cudaFuncSetAttribute(fwd_mma, cudaFuncAttributeMaxDynamicSharedMemorySize, PIPE_SMEM);
    cudaFuncSetAttribute(gram_mma, cudaFuncAttributeMaxDynamicSharedMemorySize, PIPE_SMEM);

    wsplit_kernel<<<dim3(16, 16, 2), dim3(32, 8)>>>(W, Wr);
    ssplit_kernel<<<dim3(NB / 128, ND / 32, 2), 256>>>(S, P);
    fwd_mma<<<dim3(ND / 128, NB / 128, 2), 256, PIPE_SMEM>>>();
    gram_mma<<<dim3(10, NSPLIT_G, 2), 256, PIPE_SMEM>>>();
    ln_kernel<<<NB, 256>>>(out, rg, rb, ag, ab);
    update_kernel<<<128, 256>>>(out, W, Wr, alpha, decay);
}

// round 5
// speedup vs baseline: 2.3127x; 1.0643x over previous
#include <cuda_runtime.h>
#include <cuda_bf16.h>
#include <cstdint>

#define NB 32768
#define ND 512
#define NSPLIT_G 32
#define KSPLIT_G (NB / NSPLIT_G)   // 1024 elements of K per gram split

#define N_GRAM_JOBS (2 * 10 * NSPLIT_G)   // 640, 32 stages each
#define N_FWD_JOBS  (2 * (NB / 128) * (ND / 128))  // 2048, 16 stages each

// ---------------------------------------------------------------------------
// Scratch (device globals: no allocation allowed)
// ---------------------------------------------------------------------------
__device__ float g_stim[(size_t)NB * ND];                    // 64 MB
__device__ float g_rec[(size_t)NB * ND];                     // 64 MB
__device__ __nv_bfloat16 g_s_split[2][(size_t)NB * 1024];    // 128 MB  [b][hi|lo]
__device__ __nv_bfloat16 g_st_split[2][(size_t)ND * 2 * NB]; // 128 MB  [i][hi|lo over b]
__device__ __nv_bfloat16 g_wt_split[2][(size_t)ND * 1024];   // 2 MB    Wt[n][hi|lo over k]
__device__ float g_gram[2][NSPLIT_G][ND * ND];               // 67 MB   split-K partials

// ---------------------------------------------------------------------------
// PTX helpers (sm_80+ compatible: cp.async, ldmatrix, mma.sync bf16)
// ---------------------------------------------------------------------------
__device__ __forceinline__ uint32_t smem_to_u32(const void* p) {
    uint32_t a;
    asm("{ .reg .u64 t; cvta.to.shared.u64 t, %1; cvt.u32.u64 %0, t; }"
        : "=r"(a) : "l"(p));
    return a;
}

#define CP16(dst, src) \
    asm volatile("cp.async.cg.shared.global [%0], [%1], 16;" :: "r"(dst), "l"(src))
#define CP_COMMIT() asm volatile("cp.async.commit_group;")
#define CP_WAIT0() asm volatile("cp.async.wait_group 0;")
#define CP_WAIT1() asm volatile("cp.async.wait_group 1;")

__device__ __forceinline__ void ldsm4(uint32_t* r, uint32_t addr) {
    asm volatile("ldmatrix.sync.aligned.m8n8.x4.shared.b16 {%0,%1,%2,%3}, [%4];"
                 : "=r"(r[0]), "=r"(r[1]), "=r"(r[2]), "=r"(r[3]) : "r"(addr));
}

__device__ __forceinline__ void mma16816(float* d, const uint32_t* a, const uint32_t* b) {
    asm volatile(
        "mma.sync.aligned.m16n8k16.row.col.f32.bf16.bf16.f32 "
        "{%0,%1,%2,%3}, {%4,%5,%6,%7}, {%8,%9}, {%0,%1,%2,%3};"
        : "+f"(d[0]), "+f"(d[1]), "+f"(d[2]), "+f"(d[3])
        : "r"(a[0]), "r"(a[1]), "r"(a[2]), "r"(a[3]), "r"(b[0]), "r"(b[1]));
}

// smem tile: 128 rows x 32 bf16 (64B), padded stride 80B (conflict-free ldmatrix)
#define TROWB 80
#define TILEB (128 * TROWB)        // 10240 B
#define STAGEB (4 * TILEB)         // Ahi|Alo|Bhi|Blo = 40960 B
#define PIPE_SMEM (2 * STAGEB)     // 81920 B dynamic

// load one stage: 4 tiles (Ahi, Alo, Bhi, Blo), 128x32 bf16 each, via cp.async
__device__ __forceinline__ void load_stage(uint32_t sm,
                                           const __nv_bfloat16* Ahi,
                                           const __nv_bfloat16* Alo, size_t sA,
                                           const __nv_bfloat16* Bhi,
                                           const __nv_bfloat16* Blo, size_t sB, int t) {
#pragma unroll
    for (int r = 0; r < 2; r++) {
        int c = t + r * 256;
        int row = c >> 2, ch = c & 3;
        uint32_t d = row * TROWB + ch * 16;
        size_t ga = (size_t)row * sA + ch * 8;
        size_t gb = (size_t)row * sB + ch * 8;
        CP16(sm + d, Ahi + ga);
        CP16(sm + TILEB + d, Alo + ga);
        CP16(sm + 2 * TILEB + d, Bhi + gb);
        CP16(sm + 3 * TILEB + d, Blo + gb);
    }
}

// per-thread ldmatrix offsets (byte offsets within a tile buffer)
struct LaneOff {
    uint32_t a[2];   // mt = 0,1
    uint32_t b[4];   // nt pairs 0..3
};
__device__ __forceinline__ LaneOff make_offsets(int t) {
    int w = t >> 5, l = t & 31;
    int wm = w & 3, wn = w >> 2;
    int mat = l >> 3, lrow = l & 7;
    LaneOff o;
#pragma unroll
    for (int mt = 0; mt < 2; mt++) {
        int m = wm * 32 + mt * 16 + (mat & 1) * 8 + lrow;
        int k = (mat >> 1) * 8;
        o.a[mt] = m * TROWB + k * 2;
    }
#pragma unroll
    for (int q = 0; q < 4; q++) {
        int n = wn * 64 + q * 16 + (l >> 4) * 8 + lrow;
        int k = ((l >> 3) & 1) * 8;
        o.b[q] = n * TROWB + k * 2;
    }
    return o;
}

// all 3 split combos on one resident stage with fragment reuse:
//   HH (aHi*bHi), HL (aHi*bLo, reuse aHi), LH (aLo*bHi, reuse bHi)
__device__ __forceinline__ void compute_stage(uint32_t sm, const LaneOff& o,
                                              float acc[2][8][4]) {
    const uint32_t Ahi = sm, Alo = sm + TILEB;
    const uint32_t Bhi = sm + 2 * TILEB, Blo = sm + 3 * TILEB;
#pragma unroll
    for (int ks = 0; ks < 2; ks++) {
        uint32_t ah[2][4], al[2][4], bh[4][4], bl[4][4];
        ldsm4(ah[0], Ahi + o.a[0] + ks * 32);
        ldsm4(ah[1], Ahi + o.a[1] + ks * 32);
#pragma unroll
        for (int q = 0; q < 4; q++) ldsm4(bh[q], Bhi + o.b[q] + ks * 32);
#pragma unroll
        for (int mt = 0; mt < 2; mt++)
#pragma unroll
            for (int nt = 0; nt < 8; nt++)
                mma16816(acc[mt][nt], ah[mt], &bh[nt >> 1][(nt & 1) * 2]);
#pragma unroll
        for (int q = 0; q < 4; q++) ldsm4(bl[q], Blo + o.b[q] + ks * 32);
#pragma unroll
        for (int mt = 0; mt < 2; mt++)
#pragma unroll
            for (int nt = 0; nt < 8; nt++)
                mma16816(acc[mt][nt], ah[mt], &bl[nt >> 1][(nt & 1) * 2]);
        ldsm4(al[0], Alo + o.a[0] + ks * 32);
        ldsm4(al[1], Alo + o.a[1] + ks * 32);
#pragma unroll
        for (int mt = 0; mt < 2; mt++)
#pragma unroll
            for (int nt = 0; nt < 8; nt++)
                mma16816(acc[mt][nt], al[mt], &bh[nt >> 1][(nt & 1) * 2]);
    }
}

// ---------------------------------------------------------------------------
// P1: W/Wr -> transposed bf16 split  Wt[n][k] (k: 0..511 hi, 512..1023 lo)
// ---------------------------------------------------------------------------
__global__ void wsplit_kernel(const float* __restrict__ W, const float* __restrict__ Wr) {
    __shared__ float tile[32][33];
    int mat = blockIdx.z;
    const float* src = mat ? Wr : W;
    __nv_bfloat16* dst = g_wt_split[mat];
    int k0 = blockIdx.x * 32, n0 = blockIdx.y * 32;
    int tx = threadIdx.x, ty = threadIdx.y;
    for (int ry = ty; ry < 32; ry += 8)
        tile[ry][tx] = src[(size_t)(k0 + ry) * ND + n0 + tx];
    __syncthreads();
    for (int ry = ty; ry < 32; ry += 8) {
        float v = tile[tx][ry];
        __nv_bfloat16 hi = __float2bfloat16(v);
        __nv_bfloat16 lo = __float2bfloat16(v - __bfloat162float(hi));
        dst[(size_t)(n0 + ry) * 1024 + k0 + tx] = hi;
        dst[(size_t)(n0 + ry) * 1024 + 512 + k0 + tx] = lo;
    }
}

// ---------------------------------------------------------------------------
// P2: S/P -> row-major bf16 split [b][1024] and transposed split [i][hi|lo over b]
// ---------------------------------------------------------------------------
__global__ __launch_bounds__(256) void ssplit_kernel(const float* __restrict__ S,
                                                     const float* __restrict__ P) {
    __shared__ float tile[128][33];
    int mat = blockIdx.z;
    const float* src = mat ? P : S;
    __nv_bfloat16* drow = g_s_split[mat];
    __nv_bfloat16* dcol = g_st_split[mat];
    int b0 = blockIdx.x * 128, c0 = blockIdx.y * 32;
    int t = threadIdx.x;
#pragma unroll
    for (int j = 0; j < 16; j++) {
        int idx = t + 256 * j;
        int r = idx >> 5, c = idx & 31;
        tile[r][c] = src[(size_t)(b0 + r) * ND + c0 + c];
    }
    __syncthreads();
#pragma unroll
    for (int j = 0; j < 16; j++) {
        int idx = t + 256 * j;
        int r = idx >> 5, c = idx & 31;
        float v = tile[r][c];
        __nv_bfloat16 hi = __float2bfloat16(v);
        __nv_bfloat16 lo = __float2bfloat16(v - __bfloat162float(hi));
        drow[(size_t)(b0 + r) * 1024 + c0 + c] = hi;
        drow[(size_t)(b0 + r) * 1024 + 512 + c0 + c] = lo;
    }
#pragma unroll
    for (int j = 0; j < 16; j++) {
        int idx = t + 256 * j;
        int il = idx >> 7, bl = idx & 127;
        float v = tile[bl][il];
        __nv_bfloat16 hi = __float2bfloat16(v);
        __nv_bfloat16 lo = __float2bfloat16(v - __bfloat162float(hi));
        size_t rb = (size_t)(c0 + il) * (2 * NB);
        dcol[rb + b0 + bl] = hi;
        dcol[rb + NB + b0 + bl] = lo;
    }
}

// ---------------------------------------------------------------------------
// K1: unified MMA kernel. Flattened job space:
//   jobs [0, 640):   gram tiles (32 stages each)  -- scheduled first
//   jobs [640, 2688): fwd tiles (16 stages each)  -- pack the tail
// ---------------------------------------------------------------------------
__global__ __launch_bounds__(256, 2) void mma_all() {
    extern __shared__ __align__(128) char dynsm[];
    const int TI_[10] = {0, 0, 0, 0, 1, 1, 1, 2, 2, 3};
    const int TJ_[10] = {0, 1, 2, 3, 1, 2, 3, 2, 3, 3};
    int t = threadIdx.x;
    int job = blockIdx.x;

    const __nv_bfloat16 *Ah0, *Bh0;
    size_t sA, sB, loA, loB;
    float* Out;
    int nst;

    if (job < N_GRAM_JOBS) {
        int mat = job / (N_GRAM_JOBS / 2);
        int r = job % (N_GRAM_JOBS / 2);
        int tile = r / NSPLIT_G, sp = r % NSPLIT_G;
        int i0 = TI_[tile] * 128, j0 = TJ_[tile] * 128;
        const __nv_bfloat16* Sg = g_st_split[mat];
        size_t kb = (size_t)sp * KSPLIT_G;
        Ah0 = Sg + (size_t)i0 * (2 * NB) + kb;
        Bh0 = Sg + (size_t)j0 * (2 * NB) + kb;
        sA = sB = 2 * NB;
        loA = loB = NB;
        Out = g_gram[mat][sp] + (size_t)i0 * ND + j0;
        nst = KSPLIT_G / 32;            // 32
    } else {
        int f = job - N_GRAM_JOBS;
        int mat = f / (N_FWD_JOBS / 2);
        int r = f % (N_FWD_JOBS / 2);
        int n0 = (r & 3) * 128, m0 = (r >> 2) * 128;
        Ah0 = g_s_split[mat] + (size_t)m0 * 1024;
        Bh0 = g_wt_split[mat] + (size_t)n0 * 1024;
        sA = sB = 1024;
        loA = loB = 512;
        Out = (mat ? g_rec : g_stim) + (size_t)m0 * ND + n0;
        nst = ND / 32;                  // 16
    }

    uint32_t smb[2] = {smem_to_u32(dynsm), smem_to_u32(dynsm) + STAGEB};
    LaneOff o = make_offsets(t);
    float acc[2][8][4];
#pragma unroll
    for (int i = 0; i < 2; i++)
#pragma unroll
        for (int j = 0; j < 8; j++)
#pragma unroll
            for (int q = 0; q < 4; q++) acc[i][j][q] = 0.f;

    auto issue = [&](int i, int buf) {
        const __nv_bfloat16* Ab = Ah0 + i * 32;
        const __nv_bfloat16* Bb = Bh0 + i * 32;
        load_stage(smb[buf], Ab, Ab + loA, sA, Bb, Bb + loB, sB, t);
        CP_COMMIT();
    };

    issue(0, 0);
    for (int i = 0; i < nst; i++) {
        int buf = i & 1;
        if (i + 1 < nst) {
            issue(i + 1, buf ^ 1);
            CP_WAIT1();
        } else {
            CP_WAIT0();
        }
        __syncthreads();
        compute_stage(smb[buf], o, acc);
        __syncthreads();
    }

    int w = t >> 5, l = t & 31;
    int wm = w & 3, wn = w >> 2;
#pragma unroll
    for (int mt = 0; mt < 2; mt++)
#pragma unroll
        for (int nt = 0; nt < 8; nt++) {
            int m = wm * 32 + mt * 16 + (l >> 2);
            int n = wn * 64 + nt * 8 + (l & 3) * 2;
            *(float2*)&Out[(size_t)m * ND + n] = make_float2(acc[mt][nt][0], acc[mt][nt][1]);
            *(float2*)&Out[(size_t)(m + 8) * ND + n] = make_float2(acc[mt][nt][2], acc[mt][nt][3]);
        }
}

// ---------------------------------------------------------------------------
// K3: rec LN -> relu(stim + rec_norm) -> final LN. One block per row.
// ---------------------------------------------------------------------------
__device__ __forceinline__ float2 block_sum2(float2 v, float2* sbuf) {
#pragma unroll
    for (int o = 16; o > 0; o >>= 1) {
        v.x += __shfl_xor_sync(0xffffffffu, v.x, o);
        v.y += __shfl_xor_sync(0xffffffffu, v.y, o);
    }
    int w = threadIdx.x >> 5, l = threadIdx.x & 31;
    if (l == 0) sbuf[w] = v;
    __syncthreads();
    float2 r = make_float2(0.f, 0.f);
#pragma unroll
    for (int i = 0; i < 8; i++) {
        r.x += sbuf[i].x;
        r.y += sbuf[i].y;
    }
    __syncthreads();
    return r;
}

__global__ __launch_bounds__(256) void ln_kernel(float* __restrict__ out,
                                                 const float* __restrict__ rg,
                                                 const float* __restrict__ rb,
                                                 const float* __restrict__ ag,
                                                 const float* __restrict__ ab) {
    __shared__ float2 sbuf[8];
    size_t base = (size_t)blockIdx.x * ND;
    int t = threadIdx.x;

    float r0 = g_rec[base + t];
    float r1 = g_rec[base + t + 256];
    float2 s = block_sum2(make_float2(r0 + r1, r0 * r0 + r1 * r1), sbuf);
    float mu = s.x * (1.f / ND);
    float var = s.y * (1.f / ND) - mu * mu;
    float inv = rsqrtf(var + 1e-5f);
    float n0 = (r0 - mu) * inv * rg[t] + rb[t];
    float n1 = (r1 - mu) * inv * rg[t + 256] + rb[t + 256];

    float x0 = fmaxf(g_stim[base + t] + n0, 0.f);
    float x1 = fmaxf(g_stim[base + t + 256] + n1, 0.f);
    float2 s2 = block_sum2(make_float2(x0 + x1, x0 * x0 + x1 * x1), sbuf);
    float mu2 = s2.x * (1.f / ND);
    float var2 = s2.y * (1.f / ND) - mu2 * mu2;
    float inv2 = rsqrtf(var2 + 1e-5f);

    out[base + t] = (x0 - mu2) * inv2 * ag[t] + ab[t];
    out[base + t + 256] = (x1 - mu2) * inv2 * ag[t + 256] + ab[t + 256];
}

// ---------------------------------------------------------------------------
// K4: weight update: sum gram splits (mirror lower tiles), heb = G @ Wm,
//     scale, l2-normalize rows
// ---------------------------------------------------------------------------
__global__ __launch_bounds__(256) void update_kernel(float* __restrict__ out_base,
                                                     const float* __restrict__ W,
                                                     const float* __restrict__ Wr,
                                                     const float* __restrict__ alpha,
                                                     const float* __restrict__ decay) {
    int z = blockIdx.x;        // 0..127
    int mat = z >> 6;
    int i0 = (z & 63) * 8;
    const float* Wm = mat ? Wr : W;
    float* o = out_base + (size_t)NB * ND + (size_t)mat * ND * ND;

    __shared__ float g[8][ND];
    __shared__ float sv[8][ND];
    __shared__ float norms[8];

    int t = threadIdx.x;
    for (int idx = t; idx < 8 * ND; idx += 256) {
        int r = idx >> 9, c = idx & 511;
        int i = i0 + r;
        size_t off = ((i >> 7) <= (c >> 7)) ? (size_t)i * ND + c : (size_t)c * ND + i;
        float s = 0.f;
#pragma unroll 8
        for (int sp = 0; sp < NSPLIT_G; sp++) s += g_gram[mat][sp][off];
        g[r][c] = s;
    }
    __syncthreads();

    float acc[8][2] = {};
    for (int k0 = 0; k0 < ND; k0 += 8) {
        float w0[8], w1[8];
#pragma unroll
        for (int u = 0; u < 8; u++) {
            w0[u] = Wm[(size_t)(k0 + u) * ND + t];
            w1[u] = Wm[(size_t)(k0 + u) * ND + t + 256];
        }
#pragma unroll
        for (int u = 0; u < 8; u++) {
#pragma unroll
            for (int r = 0; r < 8; r++) {
                float gk = g[r][k0 + u];
                acc[r][0] = fmaf(gk, w0[u], acc[r][0]);
                acc[r][1] = fmaf(gk, w1[u], acc[r][1]);
            }
        }
    }

    float a0 = alpha[t], a1 = alpha[t + 256];
#pragma unroll
    for (int r = 0; r < 8; r++) {
        float dm = 1.f - decay[i0 + r];
        sv[r][t]       = Wm[(size_t)(i0 + r) * ND + t] * dm       + acc[r][0] * a0;
        sv[r][t + 256] = Wm[(size_t)(i0 + r) * ND + t + 256] * dm + acc[r][1] * a1;
    }
    __syncthreads();

    int w = t >> 5, l = t & 31;
    {
        float s = 0.f;
#pragma unroll
        for (int c = l; c < ND; c += 32) {
            float v = sv[w][c];
            s += v * v;
        }
#pragma unroll
        for (int o2 = 16; o2 > 0; o2 >>= 1) s += __shfl_xor_sync(0xffffffffu, s, o2);
        if (l == 0) norms[w] = fmaxf(sqrtf(s), 1e-12f);
    }
    __syncthreads();

#pragma unroll
    for (int r = 0; r < 8; r++) {
        float inv = 1.f / norms[r];
        o[(size_t)(i0 + r) * ND + t]       = sv[r][t] * inv;
        o[(size_t)(i0 + r) * ND + t + 256] = sv[r][t + 256] * inv;
    }
}

// ---------------------------------------------------------------------------
extern "C" void kernel_launch(void* const* d_in, const int* in_sizes, int n_in,
                              void* d_out, int out_size) {
    const float* S     = (const float*)d_in[0];
    const float* P     = (const float*)d_in[1];
    const float* W     = (const float*)d_in[2];
    const float* Wr    = (const float*)d_in[3];
    const float* alpha = (const float*)d_in[4];
    const float* decay = (const float*)d_in[5];
    const float* ag    = (const float*)d_in[6];
    const float* ab    = (const float*)d_in[7];
    const float* rg    = (const float*)d_in[8];
    const float* rb    = (const float*)d_in[9];
    float* out = (float*)d_out;

    cudaFuncSetAttribute(mma_all, cudaFuncAttributeMaxDynamicSharedMemorySize, PIPE_SMEM);

    wsplit_kernel<<<dim3(16, 16, 2), dim3(32, 8)>>>(W, Wr);
    ssplit_kernel<<<dim3(NB / 128, ND / 32, 2), 256>>>(S, P);
    mma_all<<<N_GRAM_JOBS + N_FWD_JOBS, 256, PIPE_SMEM>>>();
    ln_kernel<<<NB, 256>>>(out, rg, rb, ag, ab);
    update_kernel<<<128, 256>>>(out, W, Wr, alpha, decay);
}

// round 6
// speedup vs baseline: 2.8997x; 1.2538x over previous
#include <cuda_runtime.h>
#include <cuda_bf16.h>
#include <cstdint>

#define NB 32768
#define ND 512
#define NSPLIT_G 32
#define KSPLIT_G (NB / NSPLIT_G)   // 1024 elements of K per gram split

#define N_FWD_JOBS  (2 * (NB / 128) * (ND / 128))  // 2048, 16 stages, 3 combos
#define N_GRAM_JOBS (2 * 10 * NSPLIT_G)            // 640, 32 stages, hi-only

// ---------------------------------------------------------------------------
// Scratch (device globals: no allocation allowed)
// ---------------------------------------------------------------------------
__device__ float g_stim[(size_t)NB * ND];                    // 64 MB
__device__ float g_rec[(size_t)NB * ND];                     // 64 MB
__device__ __nv_bfloat16 g_s_split[2][(size_t)NB * 1024];    // 128 MB  [b][hi|lo]
__device__ __nv_bfloat16 g_st_hi[2][(size_t)ND * NB];        // 64 MB   [i][hi over b]
__device__ __nv_bfloat16 g_wt_split[2][(size_t)ND * 1024];   // 2 MB    Wt[n][hi|lo over k]
__device__ float g_gram[2][NSPLIT_G][ND * ND];               // 64 MB   split-K partials

// ---------------------------------------------------------------------------
// PTX helpers (sm_80+ compatible: cp.async, ldmatrix, mma.sync bf16)
// ---------------------------------------------------------------------------
__device__ __forceinline__ uint32_t smem_to_u32(const void* p) {
    uint32_t a;
    asm("{ .reg .u64 t; cvta.to.shared.u64 t, %1; cvt.u32.u64 %0, t; }"
        : "=r"(a) : "l"(p));
    return a;
}

#define CP16(dst, src) \
    asm volatile("cp.async.cg.shared.global [%0], [%1], 16;" :: "r"(dst), "l"(src))
#define CP_COMMIT() asm volatile("cp.async.commit_group;")
#define CP_WAIT0() asm volatile("cp.async.wait_group 0;")
#define CP_WAIT1() asm volatile("cp.async.wait_group 1;")

__device__ __forceinline__ void ldsm4(uint32_t* r, uint32_t addr) {
    asm volatile("ldmatrix.sync.aligned.m8n8.x4.shared.b16 {%0,%1,%2,%3}, [%4];"
                 : "=r"(r[0]), "=r"(r[1]), "=r"(r[2]), "=r"(r[3]) : "r"(addr));
}

__device__ __forceinline__ void mma16816(float* d, const uint32_t* a, const uint32_t* b) {
    asm volatile(
        "mma.sync.aligned.m16n8k16.row.col.f32.bf16.bf16.f32 "
        "{%0,%1,%2,%3}, {%4,%5,%6,%7}, {%8,%9}, {%0,%1,%2,%3};"
        : "+f"(d[0]), "+f"(d[1]), "+f"(d[2]), "+f"(d[3])
        : "r"(a[0]), "r"(a[1]), "r"(a[2]), "r"(a[3]), "r"(b[0]), "r"(b[1]));
}

// smem tile: 128 rows x 32 bf16 (64B), padded stride 80B (conflict-free ldmatrix)
#define TROWB 80
#define TILEB (128 * TROWB)        // 10240 B
#define STAGEB (4 * TILEB)         // Ahi|Alo|Bhi|Blo = 40960 B
#define PIPE_SMEM (2 * STAGEB)     // 81920 B dynamic

// fwd stage: 4 tiles (Ahi, Alo, Bhi, Blo)
__device__ __forceinline__ void load_stage4(uint32_t sm,
                                            const __nv_bfloat16* Ahi,
                                            const __nv_bfloat16* Alo, size_t sA,
                                            const __nv_bfloat16* Bhi,
                                            const __nv_bfloat16* Blo, size_t sB, int t) {
#pragma unroll
    for (int r = 0; r < 2; r++) {
        int c = t + r * 256;
        int row = c >> 2, ch = c & 3;
        uint32_t d = row * TROWB + ch * 16;
        size_t ga = (size_t)row * sA + ch * 8;
        size_t gb = (size_t)row * sB + ch * 8;
        CP16(sm + d, Ahi + ga);
        CP16(sm + TILEB + d, Alo + ga);
        CP16(sm + 2 * TILEB + d, Bhi + gb);
        CP16(sm + 3 * TILEB + d, Blo + gb);
    }
}

// gram stage: 2 tiles (Ahi at +0, Bhi at +TILEB)
__device__ __forceinline__ void load_stage2(uint32_t sm,
                                            const __nv_bfloat16* Ahi, size_t sA,
                                            const __nv_bfloat16* Bhi, size_t sB, int t) {
#pragma unroll
    for (int r = 0; r < 2; r++) {
        int c = t + r * 256;
        int row = c >> 2, ch = c & 3;
        uint32_t d = row * TROWB + ch * 16;
        CP16(sm + d, Ahi + (size_t)row * sA + ch * 8);
        CP16(sm + TILEB + d, Bhi + (size_t)row * sB + ch * 8);
    }
}

// per-thread ldmatrix offsets (byte offsets within a tile buffer)
struct LaneOff {
    uint32_t a[2];   // mt = 0,1
    uint32_t b[4];   // nt pairs 0..3
};
__device__ __forceinline__ LaneOff make_offsets(int t) {
    int w = t >> 5, l = t & 31;
    int wm = w & 3, wn = w >> 2;
    int mat = l >> 3, lrow = l & 7;
    LaneOff o;
#pragma unroll
    for (int mt = 0; mt < 2; mt++) {
        int m = wm * 32 + mt * 16 + (mat & 1) * 8 + lrow;
        int k = (mat >> 1) * 8;
        o.a[mt] = m * TROWB + k * 2;
    }
#pragma unroll
    for (int q = 0; q < 4; q++) {
        int n = wn * 64 + q * 16 + (l >> 4) * 8 + lrow;
        int k = ((l >> 3) & 1) * 8;
        o.b[q] = n * TROWB + k * 2;
    }
    return o;
}

// fwd: all 3 split combos with fragment reuse (HH, HL reuse aHi, LH reuse bHi)
__device__ __forceinline__ void compute_stage3(uint32_t sm, const LaneOff& o,
                                               float acc[2][8][4]) {
    const uint32_t Ahi = sm, Alo = sm + TILEB;
    const uint32_t Bhi = sm + 2 * TILEB, Blo = sm + 3 * TILEB;
#pragma unroll
    for (int ks = 0; ks < 2; ks++) {
        uint32_t ah[2][4], al[2][4], bh[4][4], bl[4][4];
        ldsm4(ah[0], Ahi + o.a[0] + ks * 32);
        ldsm4(ah[1], Ahi + o.a[1] + ks * 32);
#pragma unroll
        for (int q = 0; q < 4; q++) ldsm4(bh[q], Bhi + o.b[q] + ks * 32);
#pragma unroll
        for (int mt = 0; mt < 2; mt++)
#pragma unroll
            for (int nt = 0; nt < 8; nt++)
                mma16816(acc[mt][nt], ah[mt], &bh[nt >> 1][(nt & 1) * 2]);
#pragma unroll
        for (int q = 0; q < 4; q++) ldsm4(bl[q], Blo + o.b[q] + ks * 32);
#pragma unroll
        for (int mt = 0; mt < 2; mt++)
#pragma unroll
            for (int nt = 0; nt < 8; nt++)
                mma16816(acc[mt][nt], ah[mt], &bl[nt >> 1][(nt & 1) * 2]);
        ldsm4(al[0], Alo + o.a[0] + ks * 32);
        ldsm4(al[1], Alo + o.a[1] + ks * 32);
#pragma unroll
        for (int mt = 0; mt < 2; mt++)
#pragma unroll
            for (int nt = 0; nt < 8; nt++)
                mma16816(acc[mt][nt], al[mt], &bh[nt >> 1][(nt & 1) * 2]);
    }
}

// gram: hi*hi only
__device__ __forceinline__ void compute_stage1(uint32_t sm, const LaneOff& o,
                                               float acc[2][8][4]) {
    const uint32_t Ahi = sm, Bhi = sm + TILEB;
#pragma unroll
    for (int ks = 0; ks < 2; ks++) {
        uint32_t ah[2][4], bh[4][4];
        ldsm4(ah[0], Ahi + o.a[0] + ks * 32);
        ldsm4(ah[1], Ahi + o.a[1] + ks * 32);
#pragma unroll
        for (int q = 0; q < 4; q++) ldsm4(bh[q], Bhi + o.b[q] + ks * 32);
#pragma unroll
        for (int mt = 0; mt < 2; mt++)
#pragma unroll
            for (int nt = 0; nt < 8; nt++)
                mma16816(acc[mt][nt], ah[mt], &bh[nt >> 1][(nt & 1) * 2]);
    }
}

// ---------------------------------------------------------------------------
// P1: W/Wr -> transposed bf16 split  Wt[n][k] (k: 0..511 hi, 512..1023 lo)
// ---------------------------------------------------------------------------
__global__ void wsplit_kernel(const float* __restrict__ W, const float* __restrict__ Wr) {
    __shared__ float tile[32][33];
    int mat = blockIdx.z;
    const float* src = mat ? Wr : W;
    __nv_bfloat16* dst = g_wt_split[mat];
    int k0 = blockIdx.x * 32, n0 = blockIdx.y * 32;
    int tx = threadIdx.x, ty = threadIdx.y;
    for (int ry = ty; ry < 32; ry += 8)
        tile[ry][tx] = src[(size_t)(k0 + ry) * ND + n0 + tx];
    __syncthreads();
    for (int ry = ty; ry < 32; ry += 8) {
        float v = tile[tx][ry];
        __nv_bfloat16 hi = __float2bfloat16(v);
        __nv_bfloat16 lo = __float2bfloat16(v - __bfloat162float(hi));
        dst[(size_t)(n0 + ry) * 1024 + k0 + tx] = hi;
        dst[(size_t)(n0 + ry) * 1024 + 512 + k0 + tx] = lo;
    }
}

// ---------------------------------------------------------------------------
// P2: S/P -> row-major bf16 split [b][hi|lo] and transposed hi [i][b]
// ---------------------------------------------------------------------------
__global__ __launch_bounds__(256) void ssplit_kernel(const float* __restrict__ S,
                                                     const float* __restrict__ P) {
    __shared__ float tile[128][33];
    int mat = blockIdx.z;
    const float* src = mat ? P : S;
    __nv_bfloat16* drow = g_s_split[mat];
    __nv_bfloat16* dcol = g_st_hi[mat];
    int b0 = blockIdx.x * 128, c0 = blockIdx.y * 32;
    int t = threadIdx.x;
#pragma unroll
    for (int j = 0; j < 16; j++) {
        int idx = t + 256 * j;
        int r = idx >> 5, c = idx & 31;
        tile[r][c] = src[(size_t)(b0 + r) * ND + c0 + c];
    }
    __syncthreads();
#pragma unroll
    for (int j = 0; j < 16; j++) {
        int idx = t + 256 * j;
        int r = idx >> 5, c = idx & 31;
        float v = tile[r][c];
        __nv_bfloat16 hi = __float2bfloat16(v);
        __nv_bfloat16 lo = __float2bfloat16(v - __bfloat162float(hi));
        drow[(size_t)(b0 + r) * 1024 + c0 + c] = hi;
        drow[(size_t)(b0 + r) * 1024 + 512 + c0 + c] = lo;
    }
#pragma unroll
    for (int j = 0; j < 16; j++) {
        int idx = t + 256 * j;
        int il = idx >> 7, bl = idx & 127;
        dcol[(size_t)(c0 + il) * NB + b0 + bl] = __float2bfloat16(tile[bl][il]);
    }
}

// ---------------------------------------------------------------------------
// K1: unified MMA kernel. Flattened job space:
//   jobs [0, 2048):        fwd tiles (16 stages, 3 combos) -- long jobs first
//   jobs [2048, 2688):     gram tiles (32 stages, hi-only), sp-major for L2
// ---------------------------------------------------------------------------
__global__ __launch_bounds__(256, 2) void mma_all() {
    extern __shared__ __align__(128) char dynsm[];
    const int TI_[10] = {0, 0, 0, 0, 1, 1, 1, 2, 2, 3};
    const int TJ_[10] = {0, 1, 2, 3, 1, 2, 3, 2, 3, 3};
    int t = threadIdx.x;
    int job = blockIdx.x;

    uint32_t smb[2] = {smem_to_u32(dynsm), smem_to_u32(dynsm) + STAGEB};
    LaneOff o = make_offsets(t);
    float acc[2][8][4];
#pragma unroll
    for (int i = 0; i < 2; i++)
#pragma unroll
        for (int j = 0; j < 8; j++)
#pragma unroll
            for (int q = 0; q < 4; q++) acc[i][j][q] = 0.f;

    float* Out;

    if (job < N_FWD_JOBS) {
        int mat = job / (N_FWD_JOBS / 2);
        int r = job % (N_FWD_JOBS / 2);
        int n0 = (r & 3) * 128, m0 = (r >> 2) * 128;
        const __nv_bfloat16* Ah0 = g_s_split[mat] + (size_t)m0 * 1024;
        const __nv_bfloat16* Bh0 = g_wt_split[mat] + (size_t)n0 * 1024;
        Out = (mat ? g_rec : g_stim) + (size_t)m0 * ND + n0;
        const int nst = ND / 32;   // 16

        auto issue = [&](int i, int buf) {
            const __nv_bfloat16* Ab = Ah0 + i * 32;
            const __nv_bfloat16* Bb = Bh0 + i * 32;
            load_stage4(smb[buf], Ab, Ab + 512, 1024, Bb, Bb + 512, 1024, t);
            CP_COMMIT();
        };
        issue(0, 0);
        for (int i = 0; i < nst; i++) {
            int buf = i & 1;
            if (i + 1 < nst) {
                issue(i + 1, buf ^ 1);
                CP_WAIT1();
            } else {
                CP_WAIT0();
            }
            __syncthreads();
            compute_stage3(smb[buf], o, acc);
            __syncthreads();
        }
    } else {
        int g = job - N_FWD_JOBS;
        int mat = g / (N_GRAM_JOBS / 2);
        int r = g % (N_GRAM_JOBS / 2);
        int sp = r / 10, tile = r % 10;   // sp-major: concurrent jobs share strips
        int i0 = TI_[tile] * 128, j0 = TJ_[tile] * 128;
        const __nv_bfloat16* Sg = g_st_hi[mat];
        size_t kb = (size_t)sp * KSPLIT_G;
        const __nv_bfloat16* Ah0 = Sg + (size_t)i0 * NB + kb;
        const __nv_bfloat16* Bh0 = Sg + (size_t)j0 * NB + kb;
        Out = g_gram[mat][sp] + (size_t)i0 * ND + j0;
        const int nst = KSPLIT_G / 32;   // 32

        auto issue = [&](int i, int buf) {
            load_stage2(smb[buf], Ah0 + i * 32, NB, Bh0 + i * 32, NB, t);
            CP_COMMIT();
        };
        issue(0, 0);
        for (int i = 0; i < nst; i++) {
            int buf = i & 1;
            if (i + 1 < nst) {
                issue(i + 1, buf ^ 1);
                CP_WAIT1();
            } else {
                CP_WAIT0();
            }
            __syncthreads();
            compute_stage1(smb[buf], o, acc);
            __syncthreads();
        }
    }

    int w = t >> 5, l = t & 31;
    int wm = w & 3, wn = w >> 2;
#pragma unroll
    for (int mt = 0; mt < 2; mt++)
#pragma unroll
        for (int nt = 0; nt < 8; nt++) {
            int m = wm * 32 + mt * 16 + (l >> 2);
            int n = wn * 64 + nt * 8 + (l & 3) * 2;
            *(float2*)&Out[(size_t)m * ND + n] = make_float2(acc[mt][nt][0], acc[mt][nt][1]);
            *(float2*)&Out[(size_t)(m + 8) * ND + n] = make_float2(acc[mt][nt][2], acc[mt][nt][3]);
        }
}

// ---------------------------------------------------------------------------
// K3: rec LN -> relu(stim + rec_norm) -> final LN. 128 threads/row, float4.
// ---------------------------------------------------------------------------
__global__ __launch_bounds__(128) void ln_kernel(float* __restrict__ out,
                                                 const float* __restrict__ rg,
                                                 const float* __restrict__ rb,
                                                 const float* __restrict__ ag,
                                                 const float* __restrict__ ab) {
    __shared__ float2 sbuf[4];
    size_t base = (size_t)blockIdx.x * ND;
    int t = threadIdx.x;
    int w = t >> 5, l = t & 31;

    float4 r4 = *(const float4*)&g_rec[base + t * 4];
    float2 s = make_float2(r4.x + r4.y + r4.z + r4.w,
                           r4.x * r4.x + r4.y * r4.y + r4.z * r4.z + r4.w * r4.w);
#pragma unroll
    for (int o = 16; o > 0; o >>= 1) {
        s.x += __shfl_xor_sync(0xffffffffu, s.x, o);
        s.y += __shfl_xor_sync(0xffffffffu, s.y, o);
    }
    if (l == 0) sbuf[w] = s;
    __syncthreads();
    s = make_float2(sbuf[0].x + sbuf[1].x + sbuf[2].x + sbuf[3].x,
                    sbuf[0].y + sbuf[1].y + sbuf[2].y + sbuf[3].y);
    float mu = s.x * (1.f / ND);
    float var = s.y * (1.f / ND) - mu * mu;
    float inv = rsqrtf(var + 1e-5f);

    float4 g4 = *(const float4*)&rg[t * 4];
    float4 b4 = *(const float4*)&rb[t * 4];
    float4 st4 = *(const float4*)&g_stim[base + t * 4];
    float4 x4;
    x4.x = fmaxf(st4.x + (r4.x - mu) * inv * g4.x + b4.x, 0.f);
    x4.y = fmaxf(st4.y + (r4.y - mu) * inv * g4.y + b4.y, 0.f);
    x4.z = fmaxf(st4.z + (r4.z - mu) * inv * g4.z + b4.z, 0.f);
    x4.w = fmaxf(st4.w + (r4.w - mu) * inv * g4.w + b4.w, 0.f);

    float2 s2 = make_float2(x4.x + x4.y + x4.z + x4.w,
                            x4.x * x4.x + x4.y * x4.y + x4.z * x4.z + x4.w * x4.w);
#pragma unroll
    for (int o = 16; o > 0; o >>= 1) {
        s2.x += __shfl_xor_sync(0xffffffffu, s2.x, o);
        s2.y += __shfl_xor_sync(0xffffffffu, s2.y, o);
    }
    __syncthreads();
    if (l == 0) sbuf[w] = s2;
    __syncthreads();
    s2 = make_float2(sbuf[0].x + sbuf[1].x + sbuf[2].x + sbuf[3].x,
                     sbuf[0].y + sbuf[1].y + sbuf[2].y + sbuf[3].y);
    float mu2 = s2.x * (1.f / ND);
    float var2 = s2.y * (1.f / ND) - mu2 * mu2;
    float inv2 = rsqrtf(var2 + 1e-5f);

    float4 ag4 = *(const float4*)&ag[t * 4];
    float4 ab4 = *(const float4*)&ab[t * 4];
    float4 o4;
    o4.x = (x4.x - mu2) * inv2 * ag4.x + ab4.x;
    o4.y = (x4.y - mu2) * inv2 * ag4.y + ab4.y;
    o4.z = (x4.z - mu2) * inv2 * ag4.z + ab4.z;
    o4.w = (x4.w - mu2) * inv2 * ag4.w + ab4.w;
    *(float4*)&out[base + t * 4] = o4;
}

// ---------------------------------------------------------------------------
// K4: weight update: sum gram splits (mirror lower tiles), heb = G @ Wm,
//     scale, l2-normalize rows
// ---------------------------------------------------------------------------
__global__ __launch_bounds__(256) void update_kernel(float* __restrict__ out_base,
                                                     const float* __restrict__ W,
                                                     const float* __restrict__ Wr,
                                                     const float* __restrict__ alpha,
                                                     const float* __restrict__ decay) {
    int z = blockIdx.x;        // 0..127
    int mat = z >> 6;
    int i0 = (z & 63) * 8;
    const float* Wm = mat ? Wr : W;
    float* o = out_base + (size_t)NB * ND + (size_t)mat * ND * ND;

    __shared__ float g[8][ND];
    __shared__ float sv[8][ND];
    __shared__ float norms[8];

    int t = threadIdx.x;
    for (int idx = t; idx < 8 * ND; idx += 256) {
        int r = idx >> 9, c = idx & 511;
        int i = i0 + r;
        size_t off = ((i >> 7) <= (c >> 7)) ? (size_t)i * ND + c : (size_t)c * ND + i;
        float s = 0.f;
#pragma unroll 8
        for (int sp = 0; sp < NSPLIT_G; sp++) s += g_gram[mat][sp][off];
        g[r][c] = s;
    }
    __syncthreads();

    float acc[8][2] = {};
    for (int k0 = 0; k0 < ND; k0 += 8) {
        float w0[8], w1[8];
#pragma unroll
        for (int u = 0; u < 8; u++) {
            w0[u] = Wm[(size_t)(k0 + u) * ND + t];
            w1[u] = Wm[(size_t)(k0 + u) * ND + t + 256];
        }
#pragma unroll
        for (int u = 0; u < 8; u++) {
#pragma unroll
            for (int r = 0; r < 8; r++) {
                float gk = g[r][k0 + u];
                acc[r][0] = fmaf(gk, w0[u], acc[r][0]);
                acc[r][1] = fmaf(gk, w1[u], acc[r][1]);
            }
        }
    }

    float a0 = alpha[t], a1 = alpha[t + 256];
#pragma unroll
    for (int r = 0; r < 8; r++) {
        float dm = 1.f - decay[i0 + r];
        sv[r][t]       = Wm[(size_t)(i0 + r) * ND + t] * dm       + acc[r][0] * a0;
        sv[r][t + 256] = Wm[(size_t)(i0 + r) * ND + t + 256] * dm + acc[r][1] * a1;
    }
    __syncthreads();

    int w = t >> 5, l = t & 31;
    {
        float s = 0.f;
#pragma unroll
        for (int c = l; c < ND; c += 32) {
            float v = sv[w][c];
            s += v * v;
        }
#pragma unroll
        for (int o2 = 16; o2 > 0; o2 >>= 1) s += __shfl_xor_sync(0xffffffffu, s, o2);
        if (l == 0) norms[w] = fmaxf(sqrtf(s), 1e-12f);
    }
    __syncthreads();

#pragma unroll
    for (int r = 0; r < 8; r++) {
        float inv = 1.f / norms[r];
        o[(size_t)(i0 + r) * ND + t]       = sv[r][t] * inv;
        o[(size_t)(i0 + r) * ND + t + 256] = sv[r][t + 256] * inv;
    }
}

// ---------------------------------------------------------------------------
extern "C" void kernel_launch(void* const* d_in, const int* in_sizes, int n_in,
                              void* d_out, int out_size) {
    const float* S     = (const float*)d_in[0];
    const float* P     = (const float*)d_in[1];
    const float* W     = (const float*)d_in[2];
    const float* Wr    = (const float*)d_in[3];
    const float* alpha = (const float*)d_in[4];
    const float* decay = (const float*)d_in[5];
    const float* ag    = (const float*)d_in[6];
    const float* ab    = (const float*)d_in[7];
    const float* rg    = (const float*)d_in[8];
    const float* rb    = (const float*)d_in[9];
    float* out = (float*)d_out;

    cudaFuncSetAttribute(mma_all, cudaFuncAttributeMaxDynamicSharedMemorySize, PIPE_SMEM);

    wsplit_kernel<<<dim3(16, 16, 2), dim3(32, 8)>>>(W, Wr);
    ssplit_kernel<<<dim3(NB / 128, ND / 32, 2), 256>>>(S, P);
    mma_all<<<N_FWD_JOBS + N_GRAM_JOBS, 256, PIPE_SMEM>>>();
    ln_kernel<<<NB, 128>>>(out, rg, rb, ag, ab);
    update_kernel<<<128, 256>>>(out, W, Wr, alpha, decay);
}

// round 7
// speedup vs baseline: 3.1645x; 1.0913x over previous
#include <cuda_runtime.h>
#include <cuda_bf16.h>
#include <cstdint>

#define NB 32768
#define ND 512
#define NSPLIT_G 32
#define KSPLIT_G (NB / NSPLIT_G)   // 1024 elements of K per gram split

#define N_FWD_JOBS  (2 * (NB / 128) * (ND / 128))  // 2048, 16 stages, 3 combos
#define N_GRAM_JOBS (2 * 10 * NSPLIT_G)            // 640, 32 stages, hi-only

// ---------------------------------------------------------------------------
// Scratch (device globals: no allocation allowed)
// ---------------------------------------------------------------------------
__device__ float g_stim[(size_t)NB * ND];                    // 64 MB
__device__ float g_rec[(size_t)NB * ND];                     // 64 MB
__device__ __nv_bfloat16 g_s_split[2][(size_t)NB * 1024];    // 128 MB  [b][hi|lo]
__device__ __nv_bfloat16 g_st_hi[2][(size_t)ND * NB];        // 64 MB   [i][hi over b]
__device__ __nv_bfloat16 g_wt_split[2][(size_t)ND * 1024];   // 2 MB    Wt[n][hi|lo over k]
__device__ float g_gram[2][NSPLIT_G][ND * ND];               // 64 MB   split-K partials

// ---------------------------------------------------------------------------
// PTX helpers (sm_80+ compatible: cp.async, ldmatrix, mma.sync bf16)
// ---------------------------------------------------------------------------
__device__ __forceinline__ uint32_t smem_to_u32(const void* p) {
    uint32_t a;
    asm("{ .reg .u64 t; cvta.to.shared.u64 t, %1; cvt.u32.u64 %0, t; }"
        : "=r"(a) : "l"(p));
    return a;
}

#define CP16(dst, src) \
    asm volatile("cp.async.cg.shared.global [%0], [%1], 16;" :: "r"(dst), "l"(src))
#define CP_COMMIT() asm volatile("cp.async.commit_group;")
#define CP_WAIT0() asm volatile("cp.async.wait_group 0;")

__device__ __forceinline__ void ldsm4(uint32_t* r, uint32_t addr) {
    asm volatile("ldmatrix.sync.aligned.m8n8.x4.shared.b16 {%0,%1,%2,%3}, [%4];"
                 : "=r"(r[0]), "=r"(r[1]), "=r"(r[2]), "=r"(r[3]) : "r"(addr));
}

__device__ __forceinline__ void mma16816(float* d, const uint32_t* a, const uint32_t* b) {
    asm volatile(
        "mma.sync.aligned.m16n8k16.row.col.f32.bf16.bf16.f32 "
        "{%0,%1,%2,%3}, {%4,%5,%6,%7}, {%8,%9}, {%0,%1,%2,%3};"
        : "+f"(d[0]), "+f"(d[1]), "+f"(d[2]), "+f"(d[3])
        : "r"(a[0]), "r"(a[1]), "r"(a[2]), "r"(a[3]), "r"(b[0]), "r"(b[1]));
}

// smem tile: 128 rows x 32 bf16 (64B), padded stride 80B (conflict-free ldmatrix)
#define TROWB 80
#define TILEB (128 * TROWB)        // 10240 B
#define STAGEB (4 * TILEB)         // Ahi|Alo|Bhi|Blo = 40960 B
#define PIPE_SMEM (2 * STAGEB)     // 81920 B dynamic

// fwd stage: 4 tiles (Ahi, Alo, Bhi, Blo)
__device__ __forceinline__ void load_stage4(uint32_t sm,
                                            const __nv_bfloat16* Ahi,
                                            const __nv_bfloat16* Alo, size_t sA,
                                            const __nv_bfloat16* Bhi,
                                            const __nv_bfloat16* Blo, size_t sB, int t) {
#pragma unroll
    for (int r = 0; r < 2; r++) {
        int c = t + r * 256;
        int row = c >> 2, ch = c & 3;
        uint32_t d = row * TROWB + ch * 16;
        size_t ga = (size_t)row * sA + ch * 8;
        size_t gb = (size_t)row * sB + ch * 8;
        CP16(sm + d, Ahi + ga);
        CP16(sm + TILEB + d, Alo + ga);
        CP16(sm + 2 * TILEB + d, Bhi + gb);
        CP16(sm + 3 * TILEB + d, Blo + gb);
    }
}

// gram stage: 2 tiles (Ahi at +0, Bhi at +TILEB)
__device__ __forceinline__ void load_stage2(uint32_t sm,
                                            const __nv_bfloat16* Ahi, size_t sA,
                                            const __nv_bfloat16* Bhi, size_t sB, int t) {
#pragma unroll
    for (int r = 0; r < 2; r++) {
        int c = t + r * 256;
        int row = c >> 2, ch = c & 3;
        uint32_t d = row * TROWB + ch * 16;
        CP16(sm + d, Ahi + (size_t)row * sA + ch * 8);
        CP16(sm + TILEB + d, Bhi + (size_t)row * sB + ch * 8);
    }
}

// per-thread ldmatrix offsets (byte offsets within a tile buffer)
struct LaneOff {
    uint32_t a[2];   // mt = 0,1
    uint32_t b[4];   // nt pairs 0..3
};
__device__ __forceinline__ LaneOff make_offsets(int t) {
    int w = t >> 5, l = t & 31;
    int wm = w & 3, wn = w >> 2;
    int mat = l >> 3, lrow = l & 7;
    LaneOff o;
#pragma unroll
    for (int mt = 0; mt < 2; mt++) {
        int m = wm * 32 + mt * 16 + (mat & 1) * 8 + lrow;
        int k = (mat >> 1) * 8;
        o.a[mt] = m * TROWB + k * 2;
    }
#pragma unroll
    for (int q = 0; q < 4; q++) {
        int n = wn * 64 + q * 16 + (l >> 4) * 8 + lrow;
        int k = ((l >> 3) & 1) * 8;
        o.b[q] = n * TROWB + k * 2;
    }
    return o;
}

// fwd: all 3 split combos with fragment reuse (HH, HL reuse aHi, LH reuse bHi)
__device__ __forceinline__ void compute_stage3(uint32_t sm, const LaneOff& o,
                                               float acc[2][8][4]) {
    const uint32_t Ahi = sm, Alo = sm + TILEB;
    const uint32_t Bhi = sm + 2 * TILEB, Blo = sm + 3 * TILEB;
#pragma unroll
    for (int ks = 0; ks < 2; ks++) {
        uint32_t ah[2][4], al[2][4], bh[4][4], bl[4][4];
        ldsm4(ah[0], Ahi + o.a[0] + ks * 32);
        ldsm4(ah[1], Ahi + o.a[1] + ks * 32);
#pragma unroll
        for (int q = 0; q < 4; q++) ldsm4(bh[q], Bhi + o.b[q] + ks * 32);
#pragma unroll
        for (int mt = 0; mt < 2; mt++)
#pragma unroll
            for (int nt = 0; nt < 8; nt++)
                mma16816(acc[mt][nt], ah[mt], &bh[nt >> 1][(nt & 1) * 2]);
#pragma unroll
        for (int q = 0; q < 4; q++) ldsm4(bl[q], Blo + o.b[q] + ks * 32);
#pragma unroll
        for (int mt = 0; mt < 2; mt++)
#pragma unroll
            for (int nt = 0; nt < 8; nt++)
                mma16816(acc[mt][nt], ah[mt], &bl[nt >> 1][(nt & 1) * 2]);
        ldsm4(al[0], Alo + o.a[0] + ks * 32);
        ldsm4(al[1], Alo + o.a[1] + ks * 32);
#pragma unroll
        for (int mt = 0; mt < 2; mt++)
#pragma unroll
            for (int nt = 0; nt < 8; nt++)
                mma16816(acc[mt][nt], al[mt], &bh[nt >> 1][(nt & 1) * 2]);
    }
}

// gram: hi*hi only
__device__ __forceinline__ void compute_stage1(uint32_t sm, const LaneOff& o,
                                               float acc[2][8][4]) {
    const uint32_t Ahi = sm, Bhi = sm + TILEB;
#pragma unroll
    for (int ks = 0; ks < 2; ks++) {
        uint32_t ah[2][4], bh[4][4];
        ldsm4(ah[0], Ahi + o.a[0] + ks * 32);
        ldsm4(ah[1], Ahi + o.a[1] + ks * 32);
#pragma unroll
        for (int q = 0; q < 4; q++) ldsm4(bh[q], Bhi + o.b[q] + ks * 32);
#pragma unroll
        for (int mt = 0; mt < 2; mt++)
#pragma unroll
            for (int nt = 0; nt < 8; nt++)
                mma16816(acc[mt][nt], ah[mt], &bh[nt >> 1][(nt & 1) * 2]);
    }
}

// ---------------------------------------------------------------------------
// P1: W/Wr -> transposed bf16 split  Wt[n][k] (k: 0..511 hi, 512..1023 lo)
// ---------------------------------------------------------------------------
__global__ void wsplit_kernel(const float* __restrict__ W, const float* __restrict__ Wr) {
    __shared__ float tile[32][33];
    int mat = blockIdx.z;
    const float* src = mat ? Wr : W;
    __nv_bfloat16* dst = g_wt_split[mat];
    int k0 = blockIdx.x * 32, n0 = blockIdx.y * 32;
    int tx = threadIdx.x, ty = threadIdx.y;
    for (int ry = ty; ry < 32; ry += 8)
        tile[ry][tx] = src[(size_t)(k0 + ry) * ND + n0 + tx];
    __syncthreads();
    for (int ry = ty; ry < 32; ry += 8) {
        float v = tile[tx][ry];
        __nv_bfloat16 hi = __float2bfloat16(v);
        __nv_bfloat16 lo = __float2bfloat16(v - __bfloat162float(hi));
        dst[(size_t)(n0 + ry) * 1024 + k0 + tx] = hi;
        dst[(size_t)(n0 + ry) * 1024 + 512 + k0 + tx] = lo;
    }
}

// ---------------------------------------------------------------------------
// P2: S/P -> row-major bf16 split [b][hi|lo] and transposed hi [i][b]
// ---------------------------------------------------------------------------
__global__ __launch_bounds__(256) void ssplit_kernel(const float* __restrict__ S,
                                                     const float* __restrict__ P) {
    __shared__ float tile[128][33];
    int mat = blockIdx.z;
    const float* src = mat ? P : S;
    __nv_bfloat16* drow = g_s_split[mat];
    __nv_bfloat16* dcol = g_st_hi[mat];
    int b0 = blockIdx.x * 128, c0 = blockIdx.y * 32;
    int t = threadIdx.x;
#pragma unroll
    for (int j = 0; j < 16; j++) {
        int idx = t + 256 * j;
        int r = idx >> 5, c = idx & 31;
        tile[r][c] = src[(size_t)(b0 + r) * ND + c0 + c];
    }
    __syncthreads();
#pragma unroll
    for (int j = 0; j < 16; j++) {
        int idx = t + 256 * j;
        int r = idx >> 5, c = idx & 31;
        float v = tile[r][c];
        __nv_bfloat16 hi = __float2bfloat16(v);
        __nv_bfloat16 lo = __float2bfloat16(v - __bfloat162float(hi));
        drow[(size_t)(b0 + r) * 1024 + c0 + c] = hi;
        drow[(size_t)(b0 + r) * 1024 + 512 + c0 + c] = lo;
    }
#pragma unroll
    for (int j = 0; j < 16; j++) {
        int idx = t + 256 * j;
        int il = idx >> 7, bl = idx & 127;
        dcol[(size_t)(c0 + il) * NB + b0 + bl] = __float2bfloat16(tile[bl][il]);
    }
}

// ---------------------------------------------------------------------------
// K1: unified MMA kernel, single-sync double-buffered pipeline.
//   jobs [0, 2048):    fwd tiles (16 stages, 3 combos) -- long jobs first
//   jobs [2048, 2688): gram tiles (32 stages, hi-only), sp-major for L2
// ---------------------------------------------------------------------------
__global__ __launch_bounds__(256, 2) void mma_all() {
    extern __shared__ __align__(128) char dynsm[];
    const int TI_[10] = {0, 0, 0, 0, 1, 1, 1, 2, 2, 3};
    const int TJ_[10] = {0, 1, 2, 3, 1, 2, 3, 2, 3, 3};
    int t = threadIdx.x;
    int job = blockIdx.x;

    uint32_t smb[2] = {smem_to_u32(dynsm), smem_to_u32(dynsm) + STAGEB};
    LaneOff o = make_offsets(t);
    float acc[2][8][4];
#pragma unroll
    for (int i = 0; i < 2; i++)
#pragma unroll
        for (int j = 0; j < 8; j++)
#pragma unroll
            for (int q = 0; q < 4; q++) acc[i][j][q] = 0.f;

    float* Out;

    if (job < N_FWD_JOBS) {
        int mat = job / (N_FWD_JOBS / 2);
        int r = job % (N_FWD_JOBS / 2);
        int n0 = (r & 3) * 128, m0 = (r >> 2) * 128;
        const __nv_bfloat16* Ah0 = g_s_split[mat] + (size_t)m0 * 1024;
        const __nv_bfloat16* Bh0 = g_wt_split[mat] + (size_t)n0 * 1024;
        Out = (mat ? g_rec : g_stim) + (size_t)m0 * ND + n0;
        const int nst = ND / 32;   // 16

        auto issue = [&](int i, int buf) {
            const __nv_bfloat16* Ab = Ah0 + i * 32;
            const __nv_bfloat16* Bb = Bh0 + i * 32;
            load_stage4(smb[buf], Ab, Ab + 512, 1024, Bb, Bb + 512, 1024, t);
            CP_COMMIT();
        };
        issue(0, 0);
        for (int i = 0; i < nst; i++) {
            int buf = i & 1;
            CP_WAIT0();        // buffer i landed (only outstanding group)
            __syncthreads();   // publishes buf; proves compute(i-1) done everywhere
            if (i + 1 < nst) issue(i + 1, buf ^ 1);  // overlaps compute(i)
            compute_stage3(smb[buf], o, acc);
        }
    } else {
        int g = job - N_FWD_JOBS;
        int mat = g / (N_GRAM_JOBS / 2);
        int r = g % (N_GRAM_JOBS / 2);
        int sp = r / 10, tile = r % 10;   // sp-major: concurrent jobs share strips
        int i0 = TI_[tile] * 128, j0 = TJ_[tile] * 128;
        const __nv_bfloat16* Sg = g_st_hi[mat];
        size_t kb = (size_t)sp * KSPLIT_G;
        const __nv_bfloat16* Ah0 = Sg + (size_t)i0 * NB + kb;
        const __nv_bfloat16* Bh0 = Sg + (size_t)j0 * NB + kb;
        Out = g_gram[mat][sp] + (size_t)i0 * ND + j0;
        const int nst = KSPLIT_G / 32;   // 32

        auto issue = [&](int i, int buf) {
            load_stage2(smb[buf], Ah0 + i * 32, NB, Bh0 + i * 32, NB, t);
            CP_COMMIT();
        };
        issue(0, 0);
        for (int i = 0; i < nst; i++) {
            int buf = i & 1;
            CP_WAIT0();
            __syncthreads();
            if (i + 1 < nst) issue(i + 1, buf ^ 1);
            compute_stage1(smb[buf], o, acc);
        }
    }

    __syncthreads();   // last compute done in all warps before epilogue reuse
    int w = t >> 5, l = t & 31;
    int wm = w & 3, wn = w >> 2;
#pragma unroll
    for (int mt = 0; mt < 2; mt++)
#pragma unroll
        for (int nt = 0; nt < 8; nt++) {
            int m = wm * 32 + mt * 16 + (l >> 2);
            int n = wn * 64 + nt * 8 + (l & 3) * 2;
            *(float2*)&Out[(size_t)m * ND + n] = make_float2(acc[mt][nt][0], acc[mt][nt][1]);
            *(float2*)&Out[(size_t)(m + 8) * ND + n] = make_float2(acc[mt][nt][2], acc[mt][nt][3]);
        }
}

// ---------------------------------------------------------------------------
// K3: rec LN -> relu(stim + rec_norm) -> final LN. 128 threads/row, float4.
// ---------------------------------------------------------------------------
__global__ __launch_bounds__(128) void ln_kernel(float* __restrict__ out,
                                                 const float* __restrict__ rg,
                                                 const float* __restrict__ rb,
                                                 const float* __restrict__ ag,
                                                 const float* __restrict__ ab) {
    __shared__ float2 sbuf[4];
    __shared__ float2 sbuf2[4];
    size_t base = (size_t)blockIdx.x * ND;
    int t = threadIdx.x;
    int w = t >> 5, l = t & 31;

    float4 r4 = *(const float4*)&g_rec[base + t * 4];
    float2 s = make_float2(r4.x + r4.y + r4.z + r4.w,
                           r4.x * r4.x + r4.y * r4.y + r4.z * r4.z + r4.w * r4.w);
#pragma unroll
    for (int o = 16; o > 0; o >>= 1) {
        s.x += __shfl_xor_sync(0xffffffffu, s.x, o);
        s.y += __shfl_xor_sync(0xffffffffu, s.y, o);
    }
    if (l == 0) sbuf[w] = s;
    __syncthreads();
    s = make_float2(sbuf[0].x + sbuf[1].x + sbuf[2].x + sbuf[3].x,
                    sbuf[0].y + sbuf[1].y + sbuf[2].y + sbuf[3].y);
    float mu = s.x * (1.f / ND);
    float var = s.y * (1.f / ND) - mu * mu;
    float inv = rsqrtf(var + 1e-5f);

    float4 g4 = *(const float4*)&rg[t * 4];
    float4 b4 = *(const float4*)&rb[t * 4];
    float4 st4 = *(const float4*)&g_stim[base + t * 4];
    float4 x4;
    x4.x = fmaxf(st4.x + (r4.x - mu) * inv * g4.x + b4.x, 0.f);
    x4.y = fmaxf(st4.y + (r4.y - mu) * inv * g4.y + b4.y, 0.f);
    x4.z = fmaxf(st4.z + (r4.z - mu) * inv * g4.z + b4.z, 0.f);
    x4.w = fmaxf(st4.w + (r4.w - mu) * inv * g4.w + b4.w, 0.f);

    float2 s2 = make_float2(x4.x + x4.y + x4.z + x4.w,
                            x4.x * x4.x + x4.y * x4.y + x4.z * x4.z + x4.w * x4.w);
#pragma unroll
    for (int o = 16; o > 0; o >>= 1) {
        s2.x += __shfl_xor_sync(0xffffffffu, s2.x, o);
        s2.y += __shfl_xor_sync(0xffffffffu, s2.y, o);
    }
    if (l == 0) sbuf2[w] = s2;
    __syncthreads();
    s2 = make_float2(sbuf2[0].x + sbuf2[1].x + sbuf2[2].x + sbuf2[3].x,
                     sbuf2[0].y + sbuf2[1].y + sbuf2[2].y + sbuf2[3].y);
    float mu2 = s2.x * (1.f / ND);
    float var2 = s2.y * (1.f / ND) - mu2 * mu2;
    float inv2 = rsqrtf(var2 + 1e-5f);

    float4 ag4 = *(const float4*)&ag[t * 4];
    float4 ab4 = *(const float4*)&ab[t * 4];
    float4 o4;
    o4.x = (x4.x - mu2) * inv2 * ag4.x + ab4.x;
    o4.y = (x4.y - mu2) * inv2 * ag4.y + ab4.y;
    o4.z = (x4.z - mu2) * inv2 * ag4.z + ab4.z;
    o4.w = (x4.w - mu2) * inv2 * ag4.w + ab4.w;
    *(float4*)&out[base + t * 4] = o4;
}

// ---------------------------------------------------------------------------
// K4: weight update: sum gram splits (mirror lower tiles), heb = G @ Wm,
//     scale, l2-normalize rows. 256 blocks x 4 rows.
// ---------------------------------------------------------------------------
__global__ __launch_bounds__(256) void update_kernel(float* __restrict__ out_base,
                                                     const float* __restrict__ W,
                                                     const float* __restrict__ Wr,
                                                     const float* __restrict__ alpha,
                                                     const float* __restrict__ decay) {
    int z = blockIdx.x;        // 0..255
    int mat = z >> 7;
    int i0 = (z & 127) * 4;
    const float* Wm = mat ? Wr : W;
    float* o = out_base + (size_t)NB * ND + (size_t)mat * ND * ND;

    __shared__ float g[4][ND];
    __shared__ float sv[4][ND];
    __shared__ float norms[4];

    int t = threadIdx.x;
    for (int idx = t; idx < 4 * ND; idx += 256) {
        int r = idx >> 9, c = idx & 511;
        int i = i0 + r;
        size_t off = ((i >> 7) <= (c >> 7)) ? (size_t)i * ND + c : (size_t)c * ND + i;
        float s = 0.f;
#pragma unroll 8
        for (int sp = 0; sp < NSPLIT_G; sp++) s += g_gram[mat][sp][off];
        g[r][c] = s;
    }
    __syncthreads();

    float acc[4][2] = {};
    for (int k0 = 0; k0 < ND; k0 += 8) {
        float w0[8], w1[8];
#pragma unroll
        for (int u = 0; u < 8; u++) {
            w0[u] = Wm[(size_t)(k0 + u) * ND + t];
            w1[u] = Wm[(size_t)(k0 + u) * ND + t + 256];
        }
#pragma unroll
        for (int u = 0; u < 8; u++) {
#pragma unroll
            for (int r = 0; r < 4; r++) {
                float gk = g[r][k0 + u];
                acc[r][0] = fmaf(gk, w0[u], acc[r][0]);
                acc[r][1] = fmaf(gk, w1[u], acc[r][1]);
            }
        }
    }

    float a0 = alpha[t], a1 = alpha[t + 256];
#pragma unroll
    for (int r = 0; r < 4; r++) {
        float dm = 1.f - decay[i0 + r];
        sv[r][t]       = Wm[(size_t)(i0 + r) * ND + t] * dm       + acc[r][0] * a0;
        sv[r][t + 256] = Wm[(size_t)(i0 + r) * ND + t + 256] * dm + acc[r][1] * a1;
    }
    __syncthreads();

    int w = t >> 5, l = t & 31;
    if (w < 4) {
        float s = 0.f;
#pragma unroll
        for (int c = l; c < ND; c += 32) {
            float v = sv[w][c];
            s += v * v;
        }
#pragma unroll
        for (int o2 = 16; o2 > 0; o2 >>= 1) s += __shfl_xor_sync(0xffffffffu, s, o2);
        if (l == 0) norms[w] = fmaxf(sqrtf(s), 1e-12f);
    }
    __syncthreads();

#pragma unroll
    for (int r = 0; r < 4; r++) {
        float inv = 1.f / norms[r];
        o[(size_t)(i0 + r) * ND + t]       = sv[r][t] * inv;
        o[(size_t)(i0 + r) * ND + t + 256] = sv[r][t + 256] * inv;
    }
}

// ---------------------------------------------------------------------------
extern "C" void kernel_launch(void* const* d_in, const int* in_sizes, int n_in,
                              void* d_out, int out_size) {
    const float* S     = (const float*)d_in[0];
    const float* P     = (const float*)d_in[1];
    const float* W     = (const float*)d_in[2];
    const float* Wr    = (const float*)d_in[3];
    const float* alpha = (const float*)d_in[4];
    const float* decay = (const float*)d_in[5];
    const float* ag    = (const float*)d_in[6];
    const float* ab    = (const float*)d_in[7];
    const float* rg    = (const float*)d_in[8];
    const float* rb    = (const float*)d_in[9];
    float* out = (float*)d_out;

    cudaFuncSetAttribute(mma_all, cudaFuncAttributeMaxDynamicSharedMemorySize, PIPE_SMEM);

    wsplit_kernel<<<dim3(16, 16, 2), dim3(32, 8)>>>(W, Wr);
    ssplit_kernel<<<dim3(NB / 128, ND / 32, 2), 256>>>(S, P);
    mma_all<<<N_FWD_JOBS + N_GRAM_JOBS, 256, PIPE_SMEM>>>();
    ln_kernel<<<NB, 128>>>(out, rg, rb, ag, ab);
    update_kernel<<<256, 256>>>(out, W, Wr, alpha, decay);
}